// round 3
// baseline (speedup 1.0000x reference)
#include <cuda_runtime.h>
#include <math.h>

// Problem dims
#define NB    4
#define NSEQ  2048
#define BDIM  1024
#define MTOT  (NB * NSEQ)   // 8192

// GEMM tiling
#define BM 128
#define BN 128
#define BK 16
#define TM 8
#define TN 8
#define NTHREADS 256

// Scratch (device globals: allocation-free, per harness rules)
__device__ float g_Q[(size_t)MTOT * BDIM];
__device__ float g_K[(size_t)MTOT * BDIM];
__device__ float g_V[(size_t)MTOT * BDIM];
__device__ float g_S[(size_t)NB * NSEQ * NSEQ];

// ---------------------------------------------------------------------------
// GEMM-NT: C[m,n] = scale * sum_k A[m,k] * B[n,k]
// A: [M,K] row-major, B: [N,K] row-major. Optional batch via blockIdx.z and
// strides. Optional causal block-skip (block col > block row -> skip).
// ---------------------------------------------------------------------------
__global__ __launch_bounds__(NTHREADS)
void gemm_nt_kernel(const float* __restrict__ A, const float* __restrict__ B,
                    float* __restrict__ C, int M, int N, int K, float scale,
                    long long sA, long long sB, long long sC, int causal)
{
    if (causal && (int)blockIdx.x > (int)blockIdx.y) return;

    __shared__ float As[BK][BM];
    __shared__ float Bs[BK][BN];

    const int tid = threadIdx.x;
    const int tx  = tid & 15;
    const int ty  = tid >> 4;

    const float* Ab = A + (size_t)blockIdx.z * sA + (size_t)blockIdx.y * BM * K;
    const float* Bb = B + (size_t)blockIdx.z * sB + (size_t)blockIdx.x * BN * K;
    float*       Cb = C + (size_t)blockIdx.z * sC;

    float acc[TM][TN];
    #pragma unroll
    for (int i = 0; i < TM; i++)
        #pragma unroll
        for (int j = 0; j < TN; j++) acc[i][j] = 0.f;

    for (int k0 = 0; k0 < K; k0 += BK) {
        // Load A tile (128x16) and B tile (128x16), transposed into [k][m]/[k][n]
        #pragma unroll
        for (int t = 0; t < 2; t++) {
            int f  = tid + t * NTHREADS;     // float4 id: 0..511
            int r  = f >> 2;                 // 0..127
            int cg = f & 3;                  // col group (4 floats)
            float4 va = *(const float4*)(Ab + (size_t)r * K + k0 + cg * 4);
            As[cg * 4 + 0][r] = va.x;
            As[cg * 4 + 1][r] = va.y;
            As[cg * 4 + 2][r] = va.z;
            As[cg * 4 + 3][r] = va.w;
            float4 vb = *(const float4*)(Bb + (size_t)r * K + k0 + cg * 4);
            Bs[cg * 4 + 0][r] = vb.x;
            Bs[cg * 4 + 1][r] = vb.y;
            Bs[cg * 4 + 2][r] = vb.z;
            Bs[cg * 4 + 3][r] = vb.w;
        }
        __syncthreads();

        #pragma unroll
        for (int kk = 0; kk < BK; kk++) {
            float a[TM], b[TN];
            *(float4*)(a)     = *(const float4*)&As[kk][ty * TM];
            *(float4*)(a + 4) = *(const float4*)&As[kk][ty * TM + 4];
            *(float4*)(b)     = *(const float4*)&Bs[kk][tx * TN];
            *(float4*)(b + 4) = *(const float4*)&Bs[kk][tx * TN + 4];
            #pragma unroll
            for (int i = 0; i < TM; i++)
                #pragma unroll
                for (int j = 0; j < TN; j++)
                    acc[i][j] += a[i] * b[j];
        }
        __syncthreads();
    }

    #pragma unroll
    for (int i = 0; i < TM; i++) {
        size_t off = (size_t)(blockIdx.y * BM + ty * TM + i) * N
                   + blockIdx.x * BN + tx * TN;
        float4 v0, v1;
        v0.x = acc[i][0] * scale; v0.y = acc[i][1] * scale;
        v0.z = acc[i][2] * scale; v0.w = acc[i][3] * scale;
        v1.x = acc[i][4] * scale; v1.y = acc[i][5] * scale;
        v1.z = acc[i][6] * scale; v1.w = acc[i][7] * scale;
        *(float4*)(Cb + off)     = v0;
        *(float4*)(Cb + off + 4) = v1;
    }
}

// ---------------------------------------------------------------------------
// Row softmax over causal prefix. One block per (b, q) row. Row cached in smem.
// Writes normalized probs back in place; zero-fills (q, blockEnd) so the PV
// GEMM can use a per-query-block k-limit without reading garbage.
// ---------------------------------------------------------------------------
__global__ __launch_bounds__(256)
void softmax_kernel(float* __restrict__ S)
{
    __shared__ float buf[NSEQ];
    __shared__ float red[256];

    const int tid = threadIdx.x;
    const int row = blockIdx.x;           // 0..8191
    const int b   = row >> 11;
    const int q   = row & (NSEQ - 1);
    float* srow = S + ((size_t)b * NSEQ + q) * NSEQ;
    const int len = q + 1;

    float m = -INFINITY;
    for (int j = tid; j < len; j += 256) {
        float v = srow[j];
        buf[j] = v;
        m = fmaxf(m, v);
    }
    red[tid] = m;
    __syncthreads();
    #pragma unroll
    for (int s = 128; s > 0; s >>= 1) {
        if (tid < s) red[tid] = fmaxf(red[tid], red[tid + s]);
        __syncthreads();
    }
    m = red[0];
    __syncthreads();

    float sum = 0.f;
    for (int j = tid; j < len; j += 256) {
        float e = __expf(buf[j] - m);
        buf[j] = e;
        sum += e;
    }
    red[tid] = sum;
    __syncthreads();
    #pragma unroll
    for (int s = 128; s > 0; s >>= 1) {
        if (tid < s) red[tid] += red[tid + s];
        __syncthreads();
    }
    const float inv = 1.f / red[0];

    for (int j = tid; j < len; j += 256) srow[j] = buf[j] * inv;

    // zero-fill within-diagonal-block remainder
    const int zend = ((q >> 7) + 1) << 7;   // next multiple of 128
    for (int j = len + tid; j < zend; j += 256) srow[j] = 0.f;
}

// ---------------------------------------------------------------------------
// GEMM-NN with causal k-limit: O[q,d] = sum_j P[q,j] * V[j,d], j < (qBlock+1)*128
// P: [NSEQ, NSEQ] row-major, V: [NSEQ, BDIM] row-major. Batched via blockIdx.z.
// ---------------------------------------------------------------------------
__global__ __launch_bounds__(NTHREADS)
void gemm_nn_causal_kernel(const float* __restrict__ P, const float* __restrict__ V,
                           float* __restrict__ C)
{
    __shared__ float As[BK][BM];
    __shared__ float Bs[BK][BN];

    const int tid = threadIdx.x;
    const int tx  = tid & 15;
    const int ty  = tid >> 4;

    const float* Ab = P + (size_t)blockIdx.z * NSEQ * NSEQ + (size_t)blockIdx.y * BM * NSEQ;
    const float* Bb = V + (size_t)blockIdx.z * NSEQ * BDIM;
    float*       Cb = C + (size_t)blockIdx.z * NSEQ * BDIM;

    const int kmax = (blockIdx.y + 1) * BM;   // causal limit (multiple of BK)

    float acc[TM][TN];
    #pragma unroll
    for (int i = 0; i < TM; i++)
        #pragma unroll
        for (int j = 0; j < TN; j++) acc[i][j] = 0.f;

    for (int k0 = 0; k0 < kmax; k0 += BK) {
        #pragma unroll
        for (int t = 0; t < 2; t++) {
            int f = tid + t * NTHREADS;      // 0..511
            // A tile: 128 rows x 16 cols, transpose into As[k][m]
            int ra  = f >> 2;
            int cga = f & 3;
            float4 va = *(const float4*)(Ab + (size_t)ra * NSEQ + k0 + cga * 4);
            As[cga * 4 + 0][ra] = va.x;
            As[cga * 4 + 1][ra] = va.y;
            As[cga * 4 + 2][ra] = va.z;
            As[cga * 4 + 3][ra] = va.w;
            // B tile: 16 rows x 128 cols, direct into Bs[k][n]
            int rb = f >> 5;                 // 0..15
            int cb = f & 31;                 // float4 col group
            float4 vb = *(const float4*)(Bb + (size_t)(k0 + rb) * BDIM
                                         + blockIdx.x * BN + cb * 4);
            *(float4*)&Bs[rb][cb * 4] = vb;
        }
        __syncthreads();

        #pragma unroll
        for (int kk = 0; kk < BK; kk++) {
            float a[TM], b[TN];
            *(float4*)(a)     = *(const float4*)&As[kk][ty * TM];
            *(float4*)(a + 4) = *(const float4*)&As[kk][ty * TM + 4];
            *(float4*)(b)     = *(const float4*)&Bs[kk][tx * TN];
            *(float4*)(b + 4) = *(const float4*)&Bs[kk][tx * TN + 4];
            #pragma unroll
            for (int i = 0; i < TM; i++)
                #pragma unroll
                for (int j = 0; j < TN; j++)
                    acc[i][j] += a[i] * b[j];
        }
        __syncthreads();
    }

    #pragma unroll
    for (int i = 0; i < TM; i++) {
        size_t off = (size_t)(blockIdx.y * BM + ty * TM + i) * BDIM
                   + blockIdx.x * BN + tx * TN;
        *(float4*)(Cb + off)     = *(float4*)&acc[i][0];
        *(float4*)(Cb + off + 4) = *(float4*)&acc[i][4];
    }
}

// ---------------------------------------------------------------------------
extern "C" void kernel_launch(void* const* d_in, const int* in_sizes, int n_in,
                              void* d_out, int out_size)
{
    const float* x  = (const float*)d_in[0];
    const float* Wq = (const float*)d_in[1];
    const float* Wk = (const float*)d_in[2];
    const float* Wv = (const float*)d_in[3];
    float* out = (float*)d_out;

    float *Q, *K, *V, *S;
    cudaGetSymbolAddress((void**)&Q, g_Q);
    cudaGetSymbolAddress((void**)&K, g_K);
    cudaGetSymbolAddress((void**)&V, g_V);
    cudaGetSymbolAddress((void**)&S, g_S);

    dim3 blk(NTHREADS);

    // 1) QKV projections: [8192,1024] x [1024,1024]^T
    dim3 gproj(BDIM / BN, MTOT / BM, 1);
    gemm_nt_kernel<<<gproj, blk>>>(x, Wq, Q, MTOT, BDIM, BDIM, 1.f, 0, 0, 0, 0);
    gemm_nt_kernel<<<gproj, blk>>>(x, Wk, K, MTOT, BDIM, BDIM, 1.f, 0, 0, 0, 0);
    gemm_nt_kernel<<<gproj, blk>>>(x, Wv, V, MTOT, BDIM, BDIM, 1.f, 0, 0, 0, 0);

    // 2) Scores: S = Q K^T / sqrt(1024), causal tile skip
    dim3 gs(NSEQ / BN, NSEQ / BM, NB);
    gemm_nt_kernel<<<gs, blk>>>(Q, K, S, NSEQ, NSEQ, BDIM, 0.03125f,
                                (long long)NSEQ * BDIM, (long long)NSEQ * BDIM,
                                (long long)NSEQ * NSEQ, 1);

    // 3) Causal row softmax (in place)
    softmax_kernel<<<NB * NSEQ, 256>>>(S);

    // 4) O = P V with causal k-limit
    dim3 go(BDIM / BN, NSEQ / BM, NB);
    gemm_nn_causal_kernel<<<go, blk>>>(S, V, out);
}

// round 4
// speedup vs baseline: 3.0620x; 3.0620x over previous
#include <cuda_runtime.h>
#include <math.h>

// Problem dims
#define NB    4
#define NSEQ  2048
#define BDIM  1024
#define MTOT  (NB * NSEQ)   // 8192

// Tiling
#define BM 128
#define BN 128
#define BK 32
#define SKP (BK + 4)    // 36: row-major A/B smem stride (conflict-free frag loads)
#define SNP (BN + 8)    // 136: k-major V smem stride
#define NTHREADS 256

// Scratch (device globals: allocation-free, per harness rules)
__device__ float g_Q[(size_t)MTOT * BDIM];
__device__ float g_K[(size_t)MTOT * BDIM];
__device__ float g_V[(size_t)MTOT * BDIM];
__device__ float g_S[(size_t)NB * NSEQ * NSEQ];

__device__ __forceinline__ unsigned f2t(float f) {
    unsigned u;
    asm("cvt.rna.tf32.f32 %0, %1;" : "=r"(u) : "f"(f));
    return u;
}

__device__ __forceinline__ void mma_tf32(float* c, const unsigned* a, const unsigned* b) {
    asm volatile(
        "mma.sync.aligned.m16n8k8.row.col.f32.tf32.tf32.f32 "
        "{%0,%1,%2,%3}, {%4,%5,%6,%7}, {%8,%9}, {%0,%1,%2,%3};"
        : "+f"(c[0]), "+f"(c[1]), "+f"(c[2]), "+f"(c[3])
        : "r"(a[0]), "r"(a[1]), "r"(a[2]), "r"(a[3]), "r"(b[0]), "r"(b[1]));
}

// ---------------------------------------------------------------------------
// Tensor-core GEMM-NT: C[m,n] = scale * sum_k A[m,k] * B[n,k]
// A: [M,K] row-major, B: [N,K] row-major. Batch via blockIdx.z + strides.
// causal: skip block cols > block rows.
// ---------------------------------------------------------------------------
__global__ __launch_bounds__(NTHREADS)
void gemm_nt_tc(const float* __restrict__ A, const float* __restrict__ B,
                float* __restrict__ C, int N, int K, float scale,
                long long sA, long long sB, long long sC, int causal)
{
    if (causal && (int)blockIdx.x > (int)blockIdx.y) return;

    __shared__ unsigned As[BM][SKP];
    __shared__ unsigned Bs[BN][SKP];

    const int tid  = threadIdx.x;
    const int lane = tid & 31;
    const int w    = tid >> 5;
    const int wR = w >> 2, wC = w & 3;       // warps: 2 rows x 4 cols
    const int gid = lane >> 2, tig = lane & 3;
    const int mb = wR * 64, nb = wC * 32;
    const int rb0 = tid >> 3, cg = tid & 7;  // global-load mapping

    const float* Ab = A + (size_t)blockIdx.z * sA + (size_t)blockIdx.y * BM * K;
    const float* Bb = B + (size_t)blockIdx.z * sB + (size_t)blockIdx.x * BN * K;
    float*       Cb = C + (size_t)blockIdx.z * sC;

    float acc[4][4][4];
    #pragma unroll
    for (int i = 0; i < 4; i++)
        #pragma unroll
        for (int j = 0; j < 4; j++)
            #pragma unroll
            for (int r = 0; r < 4; r++) acc[i][j][r] = 0.f;

    for (int k0 = 0; k0 < K; k0 += BK) {
        #pragma unroll
        for (int t = 0; t < 4; t++) {
            int r = rb0 + 32 * t;
            float4 va = *(const float4*)(Ab + (size_t)r * K + k0 + cg * 4);
            uint4 ua = make_uint4(f2t(va.x), f2t(va.y), f2t(va.z), f2t(va.w));
            *(uint4*)&As[r][cg * 4] = ua;
            float4 vb = *(const float4*)(Bb + (size_t)r * K + k0 + cg * 4);
            uint4 ub = make_uint4(f2t(vb.x), f2t(vb.y), f2t(vb.z), f2t(vb.w));
            *(uint4*)&Bs[r][cg * 4] = ub;
        }
        __syncthreads();

        #pragma unroll
        for (int ks = 0; ks < 4; ks++) {
            const int kk = ks * 8;
            unsigned a[4][4], b[4][2];
            #pragma unroll
            for (int mf = 0; mf < 4; mf++) {
                int m0 = mb + mf * 16;
                a[mf][0] = As[m0 + gid][kk + tig];
                a[mf][1] = As[m0 + 8 + gid][kk + tig];
                a[mf][2] = As[m0 + gid][kk + tig + 4];
                a[mf][3] = As[m0 + 8 + gid][kk + tig + 4];
            }
            #pragma unroll
            for (int nf = 0; nf < 4; nf++) {
                int n0 = nb + nf * 8;
                b[nf][0] = Bs[n0 + gid][kk + tig];
                b[nf][1] = Bs[n0 + gid][kk + tig + 4];
            }
            #pragma unroll
            for (int mf = 0; mf < 4; mf++)
                #pragma unroll
                for (int nf = 0; nf < 4; nf++)
                    mma_tf32(acc[mf][nf], a[mf], b[nf]);
        }
        __syncthreads();
    }

    #pragma unroll
    for (int mf = 0; mf < 4; mf++) {
        int row = blockIdx.y * BM + mb + mf * 16 + gid;
        #pragma unroll
        for (int nf = 0; nf < 4; nf++) {
            int col = blockIdx.x * BN + nb + nf * 8 + tig * 2;
            float2 v0 = make_float2(acc[mf][nf][0] * scale, acc[mf][nf][1] * scale);
            float2 v1 = make_float2(acc[mf][nf][2] * scale, acc[mf][nf][3] * scale);
            *(float2*)&Cb[(size_t)row * N + col]       = v0;
            *(float2*)&Cb[(size_t)(row + 8) * N + col] = v1;
        }
    }
}

// ---------------------------------------------------------------------------
// Tensor-core GEMM-NN with causal k-limit: O[q,d] = sum_j P[q,j]*V[j,d],
// j < (qBlock+1)*128. P: [NSEQ,NSEQ], V: [NSEQ,BDIM]. Batch via blockIdx.z.
// ---------------------------------------------------------------------------
__global__ __launch_bounds__(NTHREADS)
void gemm_nn_tc(const float* __restrict__ P, const float* __restrict__ V,
                float* __restrict__ C)
{
    __shared__ unsigned As[BM][SKP];
    __shared__ unsigned Bs[BK][SNP];

    const int tid  = threadIdx.x;
    const int lane = tid & 31;
    const int w    = tid >> 5;
    const int wR = w >> 2, wC = w & 3;
    const int gid = lane >> 2, tig = lane & 3;
    const int mb = wR * 64, nb = wC * 32;
    const int rb0 = tid >> 3, cg = tid & 7;     // A-tile load mapping
    const int vr0 = tid >> 5, vc = tid & 31;    // V-tile load mapping

    const float* Ab = P + (size_t)blockIdx.z * NSEQ * NSEQ + (size_t)blockIdx.y * BM * NSEQ;
    const float* Bb = V + (size_t)blockIdx.z * NSEQ * BDIM;
    float*       Cb = C + (size_t)blockIdx.z * NSEQ * BDIM;

    const int kmax = (blockIdx.y + 1) * BM;   // causal limit (multiple of BK)

    float acc[4][4][4];
    #pragma unroll
    for (int i = 0; i < 4; i++)
        #pragma unroll
        for (int j = 0; j < 4; j++)
            #pragma unroll
            for (int r = 0; r < 4; r++) acc[i][j][r] = 0.f;

    for (int k0 = 0; k0 < kmax; k0 += BK) {
        #pragma unroll
        for (int t = 0; t < 4; t++) {
            // A tile: 128 rows x 32 k, row-major
            int r = rb0 + 32 * t;
            float4 va = *(const float4*)(Ab + (size_t)r * NSEQ + k0 + cg * 4);
            uint4 ua = make_uint4(f2t(va.x), f2t(va.y), f2t(va.z), f2t(va.w));
            *(uint4*)&As[r][cg * 4] = ua;
            // V tile: 32 k-rows x 128 n, k-major
            int kr = vr0 + 8 * t;
            float4 vb = *(const float4*)(Bb + (size_t)(k0 + kr) * BDIM
                                         + blockIdx.x * BN + vc * 4);
            uint4 ub = make_uint4(f2t(vb.x), f2t(vb.y), f2t(vb.z), f2t(vb.w));
            *(uint4*)&Bs[kr][vc * 4] = ub;
        }
        __syncthreads();

        #pragma unroll
        for (int ks = 0; ks < 4; ks++) {
            const int kk = ks * 8;
            unsigned a[4][4], b[4][2];
            #pragma unroll
            for (int mf = 0; mf < 4; mf++) {
                int m0 = mb + mf * 16;
                a[mf][0] = As[m0 + gid][kk + tig];
                a[mf][1] = As[m0 + 8 + gid][kk + tig];
                a[mf][2] = As[m0 + gid][kk + tig + 4];
                a[mf][3] = As[m0 + 8 + gid][kk + tig + 4];
            }
            #pragma unroll
            for (int nf = 0; nf < 4; nf++) {
                int n0 = nb + nf * 8;
                b[nf][0] = Bs[kk + tig][n0 + gid];
                b[nf][1] = Bs[kk + tig + 4][n0 + gid];
            }
            #pragma unroll
            for (int mf = 0; mf < 4; mf++)
                #pragma unroll
                for (int nf = 0; nf < 4; nf++)
                    mma_tf32(acc[mf][nf], a[mf], b[nf]);
        }
        __syncthreads();
    }

    #pragma unroll
    for (int mf = 0; mf < 4; mf++) {
        int row = blockIdx.y * BM + mb + mf * 16 + gid;
        #pragma unroll
        for (int nf = 0; nf < 4; nf++) {
            int col = blockIdx.x * BN + nb + nf * 8 + tig * 2;
            *(float2*)&Cb[(size_t)row * BDIM + col] =
                make_float2(acc[mf][nf][0], acc[mf][nf][1]);
            *(float2*)&Cb[(size_t)(row + 8) * BDIM + col] =
                make_float2(acc[mf][nf][2], acc[mf][nf][3]);
        }
    }
}

// ---------------------------------------------------------------------------
// Row softmax over causal prefix. One block per (b,q) row, row cached in smem.
// Zero-fills up to the next 128 boundary for the PV k-limit.
// ---------------------------------------------------------------------------
__global__ __launch_bounds__(256)
void softmax_kernel(float* __restrict__ S)
{
    __shared__ float buf[NSEQ];
    __shared__ float red[256];

    const int tid = threadIdx.x;
    const int row = blockIdx.x;
    const int b   = row >> 11;
    const int q   = row & (NSEQ - 1);
    float* srow = S + ((size_t)b * NSEQ + q) * NSEQ;
    const int len = q + 1;

    float m = -INFINITY;
    for (int j = tid; j < len; j += 256) {
        float v = srow[j];
        buf[j] = v;
        m = fmaxf(m, v);
    }
    red[tid] = m;
    __syncthreads();
    #pragma unroll
    for (int s = 128; s > 0; s >>= 1) {
        if (tid < s) red[tid] = fmaxf(red[tid], red[tid + s]);
        __syncthreads();
    }
    m = red[0];
    __syncthreads();

    float sum = 0.f;
    for (int j = tid; j < len; j += 256) {
        float e = __expf(buf[j] - m);
        buf[j] = e;
        sum += e;
    }
    red[tid] = sum;
    __syncthreads();
    #pragma unroll
    for (int s = 128; s > 0; s >>= 1) {
        if (tid < s) red[tid] += red[tid + s];
        __syncthreads();
    }
    const float inv = 1.f / red[0];

    for (int j = tid; j < len; j += 256) srow[j] = buf[j] * inv;

    const int zend = ((q >> 7) + 1) << 7;
    for (int j = len + tid; j < zend; j += 256) srow[j] = 0.f;
}

// ---------------------------------------------------------------------------
extern "C" void kernel_launch(void* const* d_in, const int* in_sizes, int n_in,
                              void* d_out, int out_size)
{
    const float* x  = (const float*)d_in[0];
    const float* Wq = (const float*)d_in[1];
    const float* Wk = (const float*)d_in[2];
    const float* Wv = (const float*)d_in[3];
    float* out = (float*)d_out;

    float *Q, *K, *V, *S;
    cudaGetSymbolAddress((void**)&Q, g_Q);
    cudaGetSymbolAddress((void**)&K, g_K);
    cudaGetSymbolAddress((void**)&V, g_V);
    cudaGetSymbolAddress((void**)&S, g_S);

    dim3 blk(NTHREADS);

    // 1) QKV projections: [8192,1024] x [1024,1024]^T (tf32 tensor cores)
    dim3 gproj(BDIM / BN, MTOT / BM, 1);
    gemm_nt_tc<<<gproj, blk>>>(x, Wq, Q, BDIM, BDIM, 1.f, 0, 0, 0, 0);
    gemm_nt_tc<<<gproj, blk>>>(x, Wk, K, BDIM, BDIM, 1.f, 0, 0, 0, 0);
    gemm_nt_tc<<<gproj, blk>>>(x, Wv, V, BDIM, BDIM, 1.f, 0, 0, 0, 0);

    // 2) Scores: S = Q K^T / 32, causal tile skip
    dim3 gs(NSEQ / BN, NSEQ / BM, NB);
    gemm_nt_tc<<<gs, blk>>>(Q, K, S, NSEQ, BDIM, 0.03125f,
                            (long long)NSEQ * BDIM, (long long)NSEQ * BDIM,
                            (long long)NSEQ * NSEQ, 1);

    // 3) Causal row softmax (in place)
    softmax_kernel<<<NB * NSEQ, 256>>>(S);

    // 4) O = P V with causal k-limit
    dim3 go(BDIM / BN, NSEQ / BM, NB);
    gemm_nn_tc<<<go, blk>>>(S, V, out);
}

// round 5
// speedup vs baseline: 3.3964x; 1.1092x over previous
#include <cuda_runtime.h>
#include <math.h>

// Problem dims
#define NB    4
#define NSEQ  2048
#define BDIM  1024
#define MTOT  (NB * NSEQ)   // 8192

// Tiling
#define BM 128
#define BN 128
#define BK 32
#define SKP (BK + 4)    // 36: row-major A/B smem stride (conflict-free frag loads)
#define SNP (BN + 8)    // 136: k-major V smem stride
#define NTHREADS 256

#define SMEM_NT (2 * (BM * SKP + BN * SKP) * 4)   // 73728 B
#define SMEM_NN (2 * (BM * SKP + BK * SNP) * 4)   // 71680 B

// Scratch (device globals: allocation-free, per harness rules)
__device__ float g_Q[(size_t)MTOT * BDIM];
__device__ float g_K[(size_t)MTOT * BDIM];
__device__ float g_V[(size_t)MTOT * BDIM];
__device__ float g_S[(size_t)NB * NSEQ * NSEQ];

__device__ __forceinline__ unsigned f2t(float f) {
    unsigned u;
    asm("cvt.rna.tf32.f32 %0, %1;" : "=r"(u) : "f"(f));
    return u;
}

__device__ __forceinline__ void mma_tf32(float* c, const unsigned* a, const unsigned* b) {
    asm volatile(
        "mma.sync.aligned.m16n8k8.row.col.f32.tf32.tf32.f32 "
        "{%0,%1,%2,%3}, {%4,%5,%6,%7}, {%8,%9}, {%0,%1,%2,%3};"
        : "+f"(c[0]), "+f"(c[1]), "+f"(c[2]), "+f"(c[3])
        : "r"(a[0]), "r"(a[1]), "r"(a[2]), "r"(a[3]), "r"(b[0]), "r"(b[1]));
}

__device__ __forceinline__ void cp16(float* dst, const float* src) {
    unsigned d = (unsigned)__cvta_generic_to_shared(dst);
    asm volatile("cp.async.cg.shared.global [%0], [%1], 16;" :: "r"(d), "l"(src));
}
__device__ __forceinline__ void cp_commit() {
    asm volatile("cp.async.commit_group;");
}
template <int N>
__device__ __forceinline__ void cp_wait() {
    asm volatile("cp.async.wait_group %0;" :: "n"(N));
}

// ---------------------------------------------------------------------------
// Tensor-core GEMM-NT (double-buffered cp.async):
// C[m,n] = scale * sum_k A[m,k] * B[n,k]
// A: [M,K] row-major, B: [N,K] row-major. Batch via blockIdx.z + strides.
// causal: skip block cols > block rows.
// ---------------------------------------------------------------------------
__global__ __launch_bounds__(NTHREADS, 2)
void gemm_nt_tc(const float* __restrict__ A, const float* __restrict__ B,
                float* __restrict__ C, int N, int K, float scale,
                long long sA, long long sB, long long sC, int causal)
{
    if (causal && (int)blockIdx.x > (int)blockIdx.y) return;

    extern __shared__ float smem[];
    float* As = smem;                       // [2][BM][SKP]
    float* Bs = smem + 2 * BM * SKP;        // [2][BN][SKP]
#define ASM_(b,r,c) As[((b) * BM + (r)) * SKP + (c)]
#define BSM_(b,r,c) Bs[((b) * BN + (r)) * SKP + (c)]

    const int tid  = threadIdx.x;
    const int lane = tid & 31;
    const int w    = tid >> 5;
    const int wR = w >> 2, wC = w & 3;       // warps: 2 rows x 4 cols
    const int gid = lane >> 2, tig = lane & 3;
    const int mb = wR * 64, nb = wC * 32;
    const int rb0 = tid >> 3, cg = tid & 7;  // global-load mapping

    const float* Ab = A + (size_t)blockIdx.z * sA + (size_t)blockIdx.y * BM * K;
    const float* Bb = B + (size_t)blockIdx.z * sB + (size_t)blockIdx.x * BN * K;
    float*       Cb = C + (size_t)blockIdx.z * sC;

    float acc[4][4][4];
    #pragma unroll
    for (int i = 0; i < 4; i++)
        #pragma unroll
        for (int j = 0; j < 4; j++)
            #pragma unroll
            for (int r = 0; r < 4; r++) acc[i][j][r] = 0.f;

    const int T = K / BK;

    // prologue: tile 0 -> buf 0
    #pragma unroll
    for (int t4 = 0; t4 < 4; t4++) {
        int r = rb0 + 32 * t4;
        cp16(&ASM_(0, r, cg * 4), Ab + (size_t)r * K + cg * 4);
        cp16(&BSM_(0, r, cg * 4), Bb + (size_t)r * K + cg * 4);
    }
    cp_commit();

    for (int t = 0; t < T; t++) {
        if (t + 1 < T) {
            const int k1 = (t + 1) * BK;
            const int nbuf = (t + 1) & 1;
            #pragma unroll
            for (int t4 = 0; t4 < 4; t4++) {
                int r = rb0 + 32 * t4;
                cp16(&ASM_(nbuf, r, cg * 4), Ab + (size_t)r * K + k1 + cg * 4);
                cp16(&BSM_(nbuf, r, cg * 4), Bb + (size_t)r * K + k1 + cg * 4);
            }
            cp_commit();
            cp_wait<1>();
        } else {
            cp_wait<0>();
        }
        __syncthreads();

        const int buf = t & 1;
        #pragma unroll
        for (int ks = 0; ks < 4; ks++) {
            const int kk = ks * 8;
            unsigned a[4][4], b[4][2];
            #pragma unroll
            for (int mf = 0; mf < 4; mf++) {
                int m0 = mb + mf * 16;
                a[mf][0] = f2t(ASM_(buf, m0 + gid,     kk + tig));
                a[mf][1] = f2t(ASM_(buf, m0 + 8 + gid, kk + tig));
                a[mf][2] = f2t(ASM_(buf, m0 + gid,     kk + tig + 4));
                a[mf][3] = f2t(ASM_(buf, m0 + 8 + gid, kk + tig + 4));
            }
            #pragma unroll
            for (int nf = 0; nf < 4; nf++) {
                int n0 = nb + nf * 8;
                b[nf][0] = f2t(BSM_(buf, n0 + gid, kk + tig));
                b[nf][1] = f2t(BSM_(buf, n0 + gid, kk + tig + 4));
            }
            #pragma unroll
            for (int mf = 0; mf < 4; mf++)
                #pragma unroll
                for (int nf = 0; nf < 4; nf++)
                    mma_tf32(acc[mf][nf], a[mf], b[nf]);
        }
        __syncthreads();
    }

    #pragma unroll
    for (int mf = 0; mf < 4; mf++) {
        int row = blockIdx.y * BM + mb + mf * 16 + gid;
        #pragma unroll
        for (int nf = 0; nf < 4; nf++) {
            int col = blockIdx.x * BN + nb + nf * 8 + tig * 2;
            float2 v0 = make_float2(acc[mf][nf][0] * scale, acc[mf][nf][1] * scale);
            float2 v1 = make_float2(acc[mf][nf][2] * scale, acc[mf][nf][3] * scale);
            *(float2*)&Cb[(size_t)row * N + col]       = v0;
            *(float2*)&Cb[(size_t)(row + 8) * N + col] = v1;
        }
    }
#undef ASM_
#undef BSM_
}

// ---------------------------------------------------------------------------
// Tensor-core GEMM-NN with causal k-limit (double-buffered cp.async):
// O[q,d] = sum_j P[q,j]*V[j,d], j < (qBlock+1)*128.
// P: [NSEQ,NSEQ], V: [NSEQ,BDIM]. Batch via blockIdx.z.
// ---------------------------------------------------------------------------
__global__ __launch_bounds__(NTHREADS, 2)
void gemm_nn_tc(const float* __restrict__ P, const float* __restrict__ V,
                float* __restrict__ C)
{
    extern __shared__ float smem[];
    float* As = smem;                       // [2][BM][SKP]
    float* Bs = smem + 2 * BM * SKP;        // [2][BK][SNP]
#define ASM_(b,r,c) As[((b) * BM + (r)) * SKP + (c)]
#define BSM_(b,r,c) Bs[((b) * BK + (r)) * SNP + (c)]

    const int tid  = threadIdx.x;
    const int lane = tid & 31;
    const int w    = tid >> 5;
    const int wR = w >> 2, wC = w & 3;
    const int gid = lane >> 2, tig = lane & 3;
    const int mb = wR * 64, nb = wC * 32;
    const int rb0 = tid >> 3, cg = tid & 7;     // A-tile load mapping
    const int vr0 = tid >> 5, vc = tid & 31;    // V-tile load mapping

    const float* Ab = P + (size_t)blockIdx.z * NSEQ * NSEQ + (size_t)blockIdx.y * BM * NSEQ;
    const float* Bb = V + (size_t)blockIdx.z * NSEQ * BDIM + (size_t)blockIdx.x * BN;
    float*       Cb = C + (size_t)blockIdx.z * NSEQ * BDIM;

    const int T = (int)(blockIdx.y + 1) * BM / BK;   // causal tile count

    float acc[4][4][4];
    #pragma unroll
    for (int i = 0; i < 4; i++)
        #pragma unroll
        for (int j = 0; j < 4; j++)
            #pragma unroll
            for (int r = 0; r < 4; r++) acc[i][j][r] = 0.f;

    // prologue: tile 0 -> buf 0
    #pragma unroll
    for (int t4 = 0; t4 < 4; t4++) {
        int r  = rb0 + 32 * t4;
        int kr = vr0 + 8 * t4;
        cp16(&ASM_(0, r, cg * 4),  Ab + (size_t)r * NSEQ + cg * 4);
        cp16(&BSM_(0, kr, vc * 4), Bb + (size_t)kr * BDIM + vc * 4);
    }
    cp_commit();

    for (int t = 0; t < T; t++) {
        if (t + 1 < T) {
            const int k1 = (t + 1) * BK;
            const int nbuf = (t + 1) & 1;
            #pragma unroll
            for (int t4 = 0; t4 < 4; t4++) {
                int r  = rb0 + 32 * t4;
                int kr = vr0 + 8 * t4;
                cp16(&ASM_(nbuf, r, cg * 4),  Ab + (size_t)r * NSEQ + k1 + cg * 4);
                cp16(&BSM_(nbuf, kr, vc * 4), Bb + (size_t)(k1 + kr) * BDIM + vc * 4);
            }
            cp_commit();
            cp_wait<1>();
        } else {
            cp_wait<0>();
        }
        __syncthreads();

        const int buf = t & 1;
        #pragma unroll
        for (int ks = 0; ks < 4; ks++) {
            const int kk = ks * 8;
            unsigned a[4][4], b[4][2];
            #pragma unroll
            for (int mf = 0; mf < 4; mf++) {
                int m0 = mb + mf * 16;
                a[mf][0] = f2t(ASM_(buf, m0 + gid,     kk + tig));
                a[mf][1] = f2t(ASM_(buf, m0 + 8 + gid, kk + tig));
                a[mf][2] = f2t(ASM_(buf, m0 + gid,     kk + tig + 4));
                a[mf][3] = f2t(ASM_(buf, m0 + 8 + gid, kk + tig + 4));
            }
            #pragma unroll
            for (int nf = 0; nf < 4; nf++) {
                int n0 = nb + nf * 8;
                b[nf][0] = f2t(BSM_(buf, kk + tig,     n0 + gid));
                b[nf][1] = f2t(BSM_(buf, kk + tig + 4, n0 + gid));
            }
            #pragma unroll
            for (int mf = 0; mf < 4; mf++)
                #pragma unroll
                for (int nf = 0; nf < 4; nf++)
                    mma_tf32(acc[mf][nf], a[mf], b[nf]);
        }
        __syncthreads();
    }

    #pragma unroll
    for (int mf = 0; mf < 4; mf++) {
        int row = blockIdx.y * BM + mb + mf * 16 + gid;
        #pragma unroll
        for (int nf = 0; nf < 4; nf++) {
            int col = blockIdx.x * BN + nb + nf * 8 + tig * 2;
            *(float2*)&Cb[(size_t)row * BDIM + col] =
                make_float2(acc[mf][nf][0], acc[mf][nf][1]);
            *(float2*)&Cb[(size_t)(row + 8) * BDIM + col] =
                make_float2(acc[mf][nf][2], acc[mf][nf][3]);
        }
    }
#undef ASM_
#undef BSM_
}

// ---------------------------------------------------------------------------
// Row softmax over causal prefix. One block per (b,q) row, row cached in smem.
// Zero-fills up to the next 128 boundary for the PV k-limit.
// ---------------------------------------------------------------------------
__global__ __launch_bounds__(256)
void softmax_kernel(float* __restrict__ S)
{
    __shared__ float buf[NSEQ];
    __shared__ float red[256];

    const int tid = threadIdx.x;
    const int row = blockIdx.x;
    const int b   = row >> 11;
    const int q   = row & (NSEQ - 1);
    float* srow = S + ((size_t)b * NSEQ + q) * NSEQ;
    const int len = q + 1;

    float m = -INFINITY;
    for (int j = tid; j < len; j += 256) {
        float v = srow[j];
        buf[j] = v;
        m = fmaxf(m, v);
    }
    red[tid] = m;
    __syncthreads();
    #pragma unroll
    for (int s = 128; s > 0; s >>= 1) {
        if (tid < s) red[tid] = fmaxf(red[tid], red[tid + s]);
        __syncthreads();
    }
    m = red[0];
    __syncthreads();

    float sum = 0.f;
    for (int j = tid; j < len; j += 256) {
        float e = __expf(buf[j] - m);
        buf[j] = e;
        sum += e;
    }
    red[tid] = sum;
    __syncthreads();
    #pragma unroll
    for (int s = 128; s > 0; s >>= 1) {
        if (tid < s) red[tid] += red[tid + s];
        __syncthreads();
    }
    const float inv = 1.f / red[0];

    for (int j = tid; j < len; j += 256) srow[j] = buf[j] * inv;

    const int zend = ((q >> 7) + 1) << 7;
    for (int j = len + tid; j < zend; j += 256) srow[j] = 0.f;
}

// ---------------------------------------------------------------------------
extern "C" void kernel_launch(void* const* d_in, const int* in_sizes, int n_in,
                              void* d_out, int out_size)
{
    const float* x  = (const float*)d_in[0];
    const float* Wq = (const float*)d_in[1];
    const float* Wk = (const float*)d_in[2];
    const float* Wv = (const float*)d_in[3];
    float* out = (float*)d_out;

    float *Q, *K, *V, *S;
    cudaGetSymbolAddress((void**)&Q, g_Q);
    cudaGetSymbolAddress((void**)&K, g_K);
    cudaGetSymbolAddress((void**)&V, g_V);
    cudaGetSymbolAddress((void**)&S, g_S);

    static int attr_set = 0;
    if (!attr_set) {
        cudaFuncSetAttribute(gemm_nt_tc, cudaFuncAttributeMaxDynamicSharedMemorySize, SMEM_NT);
        cudaFuncSetAttribute(gemm_nn_tc, cudaFuncAttributeMaxDynamicSharedMemorySize, SMEM_NN);
        attr_set = 1;
    }

    dim3 blk(NTHREADS);

    // 1) QKV projections: [8192,1024] x [1024,1024]^T (tf32 tensor cores)
    dim3 gproj(BDIM / BN, MTOT / BM, 1);
    gemm_nt_tc<<<gproj, blk, SMEM_NT>>>(x, Wq, Q, BDIM, BDIM, 1.f, 0, 0, 0, 0);
    gemm_nt_tc<<<gproj, blk, SMEM_NT>>>(x, Wk, K, BDIM, BDIM, 1.f, 0, 0, 0, 0);
    gemm_nt_tc<<<gproj, blk, SMEM_NT>>>(x, Wv, V, BDIM, BDIM, 1.f, 0, 0, 0, 0);

    // 2) Scores: S = Q K^T / 32, causal tile skip
    dim3 gs(NSEQ / BN, NSEQ / BM, NB);
    gemm_nt_tc<<<gs, blk, SMEM_NT>>>(Q, K, S, NSEQ, BDIM, 0.03125f,
                                     (long long)NSEQ * BDIM, (long long)NSEQ * BDIM,
                                     (long long)NSEQ * NSEQ, 1);

    // 3) Causal row softmax (in place)
    softmax_kernel<<<NB * NSEQ, 256>>>(S);

    // 4) O = P V with causal k-limit
    dim3 go(BDIM / BN, NSEQ / BM, NB);
    gemm_nn_tc<<<go, blk, SMEM_NN>>>(S, V, out);
}

// round 7
// speedup vs baseline: 6.2330x; 1.8351x over previous
#include <cuda_runtime.h>
#include <cuda_fp16.h>
#include <math.h>
#include <stdint.h>

// Problem dims
#define NB    4
#define NSEQ  2048
#define BDIM  1024
#define MTOT  (NB * NSEQ)   // 8192

// GEMM tiling (fp16 mma.sync m16n8k16)
#define BMH 128
#define BNH 128
#define BKH 64
#define SKH (BKH + 8)          // 72 halves/row -> 144B row stride, conflict-free
#define TILEH (BMH * SKH)      // halves per operand tile
#define STAGES 3
#define GEMM_SMEM (STAGES * 2 * TILEH * 2)   // 110592 B

// Scratch (device globals: allocation-free, per harness rules)
__device__ __half g_Xh [(size_t)MTOT * BDIM];
__device__ __half g_Wqh[(size_t)BDIM * BDIM];
__device__ __half g_Wkh[(size_t)BDIM * BDIM];
__device__ __half g_Wvh[(size_t)BDIM * BDIM];
__device__ __half g_Qh [(size_t)MTOT * BDIM];
__device__ __half g_Kh [(size_t)MTOT * BDIM];
__device__ __half g_Vh [(size_t)MTOT * BDIM];
__device__ __half g_Vth[(size_t)MTOT * BDIM];
__device__ float  g_S  [(size_t)NB * NSEQ * NSEQ];
__device__ __half g_P  [(size_t)NB * NSEQ * NSEQ];

// ---------------- PTX helpers ----------------
__device__ __forceinline__ uint32_t smem_u32(const void* p) {
    uint32_t a;
    asm("{ .reg .u64 t; cvta.to.shared.u64 t, %1; cvt.u32.u64 %0, t; }" : "=r"(a) : "l"(p));
    return a;
}
__device__ __forceinline__ void cp16s(uint32_t dst, const void* src) {
    asm volatile("cp.async.cg.shared.global [%0], [%1], 16;" :: "r"(dst), "l"(src));
}
__device__ __forceinline__ void cp_commit() { asm volatile("cp.async.commit_group;"); }
template <int N>
__device__ __forceinline__ void cp_wait() { asm volatile("cp.async.wait_group %0;" :: "n"(N)); }

__device__ __forceinline__ void ldm_x4(uint32_t* r, uint32_t addr) {
    asm volatile("ldmatrix.sync.aligned.m8n8.x4.shared.b16 {%0,%1,%2,%3}, [%4];"
                 : "=r"(r[0]), "=r"(r[1]), "=r"(r[2]), "=r"(r[3]) : "r"(addr));
}
__device__ __forceinline__ void mma_f16(float* c, const uint32_t* a, const uint32_t* b) {
    asm volatile(
        "mma.sync.aligned.m16n8k16.row.col.f32.f16.f16.f32 "
        "{%0,%1,%2,%3}, {%4,%5,%6,%7}, {%8,%9}, {%0,%1,%2,%3};"
        : "+f"(c[0]), "+f"(c[1]), "+f"(c[2]), "+f"(c[3])
        : "r"(a[0]), "r"(a[1]), "r"(a[2]), "r"(a[3]), "r"(b[0]), "r"(b[1]));
}

// ---------------------------------------------------------------------------
// fp16 tensor-core GEMM-NT, 3-stage cp.async pipeline:
// C[m,n] = scale * sum_k A[m,k] * B[n,k];  A:[M,K], B:[N,K] half, K-major.
// causal: skip tiles bx>by.  klimit: K limited to (by+1)*BMH (PV causal).
// out_half: C is __half (QKV proj), else float.
// ---------------------------------------------------------------------------
__global__ __launch_bounds__(256, 2)
void gemm_h16(const __half* __restrict__ A, const __half* __restrict__ B,
              void* __restrict__ Cv, int N, int K, float scale,
              long long sA, long long sB, long long sC,
              int causal, int klimit, int out_half)
{
    if (causal && (int)blockIdx.x > (int)blockIdx.y) return;

    extern __shared__ __half sm[];
    const int tid  = threadIdx.x;
    const int lane = tid & 31;
    const int w    = tid >> 5;
    const int wR = w >> 2, wC = w & 3;       // 2 x 4 warps
    const int gid = lane >> 2, tig = lane & 3;
    const int mb = wR * 64, nb = wC * 32;

    const __half* Ab = A + (size_t)blockIdx.z * sA + (size_t)blockIdx.y * BMH * K;
    const __half* Bb = B + (size_t)blockIdx.z * sB + (size_t)blockIdx.x * BNH * K;

    const int T = klimit ? (int)(blockIdx.y + 1) * (BMH / BKH) : K / BKH;

    // per-thread constant pieces of addressing
    const int ldr = tid >> 3, ldc = tid & 7;   // loader: row, 16B-chunk
    const uint32_t sm0 = smem_u32(sm);

    auto load_tile = [&](int t) {
        const int buf = t % STAGES;
        const uint32_t as = sm0 + buf * 2 * TILEH * 2;
        const uint32_t bs = as + TILEH * 2;
        const int k0 = t * BKH;
        const uint32_t off = (uint32_t)ldr * (SKH * 2) + ldc * 16;
        const __half* asrc = Ab + (size_t)ldr * K + k0 + ldc * 8;
        const __half* bsrc = Bb + (size_t)ldr * K + k0 + ldc * 8;
        #pragma unroll
        for (int i = 0; i < 4; i++) {
            cp16s(as + off + i * 32 * (SKH * 2), asrc + (size_t)32 * i * K);
            cp16s(bs + off + i * 32 * (SKH * 2), bsrc + (size_t)32 * i * K);
        }
        cp_commit();
    };

    float acc[4][4][4];
    #pragma unroll
    for (int i = 0; i < 4; i++)
        #pragma unroll
        for (int j = 0; j < 4; j++)
            #pragma unroll
            for (int r = 0; r < 4; r++) acc[i][j][r] = 0.f;

    load_tile(0);
    load_tile(1);

    // ldmatrix lane address pieces: row m0+(lane&15), k-half offset 8*(lane>>4)
    const uint32_t a_lane_off = (uint32_t)(mb + (lane & 15)) * (SKH * 2)
                              + (uint32_t)(lane >> 4) * 16;

    for (int u = 0; u < T; u++) {
        if (u + 1 < T) cp_wait<1>(); else cp_wait<0>();
        __syncthreads();
        if (u + 2 < T) load_tile(u + 2);

        const int buf = u % STAGES;
        const uint32_t as = sm0 + buf * 2 * TILEH * 2;
        const __half* bsp = sm + buf * 2 * TILEH + TILEH;

        #pragma unroll
        for (int ks = 0; ks < 4; ks++) {
            const int kk = ks * 16;
            uint32_t a[4][4], b[4][2];
            #pragma unroll
            for (int mf = 0; mf < 4; mf++)
                ldm_x4(a[mf], as + a_lane_off + (uint32_t)(mf * 16) * (SKH * 2) + kk * 2);
            #pragma unroll
            for (int nf = 0; nf < 4; nf++) {
                const __half* bp = bsp + (size_t)(nb + nf * 8 + gid) * SKH + kk + 2 * tig;
                b[nf][0] = *(const uint32_t*)bp;
                b[nf][1] = *(const uint32_t*)(bp + 8);
            }
            #pragma unroll
            for (int mf = 0; mf < 4; mf++)
                #pragma unroll
                for (int nf = 0; nf < 4; nf++)
                    mma_f16(acc[mf][nf], a[mf], b[nf]);
        }
    }

    // epilogue
    if (out_half) {
        __half* Cb = (__half*)Cv + (size_t)blockIdx.z * sC;
        #pragma unroll
        for (int mf = 0; mf < 4; mf++) {
            int row = blockIdx.y * BMH + mb + mf * 16 + gid;
            #pragma unroll
            for (int nf = 0; nf < 4; nf++) {
                int col = blockIdx.x * BNH + nb + nf * 8 + tig * 2;
                *(__half2*)&Cb[(size_t)row * N + col] =
                    __floats2half2_rn(acc[mf][nf][0] * scale, acc[mf][nf][1] * scale);
                *(__half2*)&Cb[(size_t)(row + 8) * N + col] =
                    __floats2half2_rn(acc[mf][nf][2] * scale, acc[mf][nf][3] * scale);
            }
        }
    } else {
        float* Cb = (float*)Cv + (size_t)blockIdx.z * sC;
        #pragma unroll
        for (int mf = 0; mf < 4; mf++) {
            int row = blockIdx.y * BMH + mb + mf * 16 + gid;
            #pragma unroll
            for (int nf = 0; nf < 4; nf++) {
                int col = blockIdx.x * BNH + nb + nf * 8 + tig * 2;
                *(float2*)&Cb[(size_t)row * N + col] =
                    make_float2(acc[mf][nf][0] * scale, acc[mf][nf][1] * scale);
                *(float2*)&Cb[(size_t)(row + 8) * N + col] =
                    make_float2(acc[mf][nf][2] * scale, acc[mf][nf][3] * scale);
            }
        }
    }
}

// ---------------------------------------------------------------------------
// Elementwise float -> half
// ---------------------------------------------------------------------------
__global__ void cvt_h_kernel(const float* __restrict__ in, __half* __restrict__ out,
                             long long n)
{
    long long i = (long long)blockIdx.x * blockDim.x + threadIdx.x;
    long long stride = (long long)gridDim.x * blockDim.x;
    for (; i < n; i += stride)
        out[i] = __float2half_rn(in[i]);
}

// ---------------------------------------------------------------------------
// Per-batch transpose (half): Vt[b][d][t] = V[b][t][d]
// ---------------------------------------------------------------------------
__global__ __launch_bounds__(256)
void transpose_h_kernel(const __half* __restrict__ V, __half* __restrict__ Vt)
{
    __shared__ __half tb[32][34];
    const int b  = blockIdx.z;
    const int t0 = blockIdx.x * 32;
    const int d0 = blockIdx.y * 32;
    const __half* Vb  = V  + (size_t)b * NSEQ * BDIM;
    __half*       Vtb = Vt + (size_t)b * BDIM * NSEQ;
    const int x = threadIdx.x & 31, y = threadIdx.x >> 5;   // 32 x 8
    #pragma unroll
    for (int i = 0; i < 32; i += 8)
        tb[y + i][x] = Vb[(size_t)(t0 + y + i) * BDIM + d0 + x];
    __syncthreads();
    #pragma unroll
    for (int i = 0; i < 32; i += 8)
        Vtb[(size_t)(d0 + y + i) * NSEQ + t0 + x] = tb[x][y + i];
}

// ---------------------------------------------------------------------------
// Row softmax over causal prefix: reads fp32 scores, writes half probs.
// Zero-fills P to the next 128 boundary for the PV k-limit.
// ---------------------------------------------------------------------------
__global__ __launch_bounds__(256)
void softmax_kernel(const float* __restrict__ S, __half* __restrict__ P)
{
    __shared__ float buf[NSEQ];
    __shared__ float red[256];

    const int tid = threadIdx.x;
    const int row = blockIdx.x;
    const int b   = row >> 11;
    const int q   = row & (NSEQ - 1);
    const float* srow = S + ((size_t)b * NSEQ + q) * NSEQ;
    __half*      prow = P + ((size_t)b * NSEQ + q) * NSEQ;
    const int len = q + 1;

    float m = -INFINITY;
    for (int j = tid; j < len; j += 256) {
        float v = srow[j];
        buf[j] = v;
        m = fmaxf(m, v);
    }
    red[tid] = m;
    __syncthreads();
    #pragma unroll
    for (int s = 128; s > 0; s >>= 1) {
        if (tid < s) red[tid] = fmaxf(red[tid], red[tid + s]);
        __syncthreads();
    }
    m = red[0];
    __syncthreads();

    float sum = 0.f;
    for (int j = tid; j < len; j += 256) {
        float e = __expf(buf[j] - m);
        buf[j] = e;
        sum += e;
    }
    red[tid] = sum;
    __syncthreads();
    #pragma unroll
    for (int s = 128; s > 0; s >>= 1) {
        if (tid < s) red[tid] += red[tid + s];
        __syncthreads();
    }
    const float inv = 1.f / red[0];

    for (int j = tid; j < len; j += 256)
        prow[j] = __float2half_rn(buf[j] * inv);

    const int zend = ((q >> 7) + 1) << 7;
    for (int j = len + tid; j < zend; j += 256) prow[j] = __float2half_rn(0.f);
}

// ---------------------------------------------------------------------------
extern "C" void kernel_launch(void* const* d_in, const int* in_sizes, int n_in,
                              void* d_out, int out_size)
{
    const float* x  = (const float*)d_in[0];
    const float* Wq = (const float*)d_in[1];
    const float* Wk = (const float*)d_in[2];
    const float* Wv = (const float*)d_in[3];
    float* out = (float*)d_out;

    __half *Xh, *Wqh, *Wkh, *Wvh, *Qh, *Kh, *Vh, *Vth, *P;
    float* S;
    cudaGetSymbolAddress((void**)&Xh,  g_Xh);
    cudaGetSymbolAddress((void**)&Wqh, g_Wqh);
    cudaGetSymbolAddress((void**)&Wkh, g_Wkh);
    cudaGetSymbolAddress((void**)&Wvh, g_Wvh);
    cudaGetSymbolAddress((void**)&Qh,  g_Qh);
    cudaGetSymbolAddress((void**)&Kh,  g_Kh);
    cudaGetSymbolAddress((void**)&Vh,  g_Vh);
    cudaGetSymbolAddress((void**)&Vth, g_Vth);
    cudaGetSymbolAddress((void**)&S,   g_S);
    cudaGetSymbolAddress((void**)&P,   g_P);

    static int attr_set = 0;
    if (!attr_set) {
        cudaFuncSetAttribute(gemm_h16, cudaFuncAttributeMaxDynamicSharedMemorySize, GEMM_SMEM);
        attr_set = 1;
    }

    // 0) inputs -> half (rounding point identical in spirit to tf32 R5 path)
    cvt_h_kernel<<<1024, 256>>>(x,  Xh,  (long long)MTOT * BDIM);
    cvt_h_kernel<<<512,  256>>>(Wq, Wqh, (long long)BDIM * BDIM);
    cvt_h_kernel<<<512,  256>>>(Wk, Wkh, (long long)BDIM * BDIM);
    cvt_h_kernel<<<512,  256>>>(Wv, Wvh, (long long)BDIM * BDIM);

    // 1) QKV projections -> half outputs
    dim3 gproj(BDIM / BNH, MTOT / BMH, 1);
    gemm_h16<<<gproj, 256, GEMM_SMEM>>>(Xh, Wqh, Qh, BDIM, BDIM, 1.f, 0, 0, 0, 0, 0, 1);
    gemm_h16<<<gproj, 256, GEMM_SMEM>>>(Xh, Wkh, Kh, BDIM, BDIM, 1.f, 0, 0, 0, 0, 0, 1);
    gemm_h16<<<gproj, 256, GEMM_SMEM>>>(Xh, Wvh, Vh, BDIM, BDIM, 1.f, 0, 0, 0, 0, 0, 1);

    // 2) V -> Vt (half, per batch [BDIM][NSEQ])
    transpose_h_kernel<<<dim3(NSEQ / 32, BDIM / 32, NB), 256>>>(Vh, Vth);

    // 3) Scores: S = Q K^T / 32 (fp32 out), causal tile skip
    dim3 gs(NSEQ / BNH, NSEQ / BMH, NB);
    gemm_h16<<<gs, 256, GEMM_SMEM>>>(Qh, Kh, S, NSEQ, BDIM, 0.03125f,
                                     (long long)NSEQ * BDIM, (long long)NSEQ * BDIM,
                                     (long long)NSEQ * NSEQ, 1, 0, 0);

    // 4) causal softmax: fp32 scores -> half probs (zero-filled to 128)
    softmax_kernel<<<NB * NSEQ, 256>>>(S, P);

    // 5) O = P Vt^T with causal k-limit (fp32 out)
    dim3 go(BDIM / BNH, NSEQ / BMH, NB);
    gemm_h16<<<go, 256, GEMM_SMEM>>>(P, Vth, out, BDIM, NSEQ, 1.f,
                                     (long long)NSEQ * NSEQ, (long long)BDIM * NSEQ,
                                     (long long)NSEQ * BDIM, 0, 1, 0);
}

// round 10
// speedup vs baseline: 6.7607x; 1.0847x over previous
#include <cuda_runtime.h>
#include <cuda_fp16.h>
#include <math.h>
#include <stdint.h>

// Problem dims
#define NB    4
#define NSEQ  2048
#define BDIM  1024
#define MTOT  (NB * NSEQ)   // 8192

// GEMM tiling (fp16 mma.sync m16n8k16)
#define BMH 128
#define BNH 128
#define BKH 64
#define SKH 72                 // halves/row (64 + 8 pad) -> 144B stride
#define SKB (SKH * 2)          // row stride bytes
#define TILEH (BMH * SKH)      // halves per operand tile
#define STAGES 3
#define GEMM_SMEM (STAGES * 2 * TILEH * 2)   // 110592 B

// Scratch (device globals: allocation-free, per harness rules)
__device__ __half g_Xh [(size_t)MTOT * BDIM];
__device__ __half g_Wqh[(size_t)BDIM * BDIM];
__device__ __half g_Wkh[(size_t)BDIM * BDIM];
__device__ __half g_Wvh[(size_t)BDIM * BDIM];
__device__ __half g_Qh [(size_t)MTOT * BDIM];
__device__ __half g_Kh [(size_t)MTOT * BDIM];
__device__ __half g_Vth[(size_t)MTOT * BDIM];   // [b][d][t]
__device__ float  g_S  [(size_t)NB * NSEQ * NSEQ];
__device__ __half g_P  [(size_t)NB * NSEQ * NSEQ];

// ---------------- PTX helpers ----------------
__device__ __forceinline__ uint32_t smem_u32(const void* p) {
    uint32_t a;
    asm("{ .reg .u64 t; cvta.to.shared.u64 t, %1; cvt.u32.u64 %0, t; }" : "=r"(a) : "l"(p));
    return a;
}
__device__ __forceinline__ void cp16s(uint32_t dst, const void* src) {
    asm volatile("cp.async.cg.shared.global [%0], [%1], 16;" :: "r"(dst), "l"(src));
}
__device__ __forceinline__ void cp_commit() { asm volatile("cp.async.commit_group;"); }
template <int N>
__device__ __forceinline__ void cp_wait() { asm volatile("cp.async.wait_group %0;" :: "n"(N)); }

__device__ __forceinline__ void ldm_x4(uint32_t* r, uint32_t addr) {
    asm volatile("ldmatrix.sync.aligned.m8n8.x4.shared.b16 {%0,%1,%2,%3}, [%4];"
                 : "=r"(r[0]), "=r"(r[1]), "=r"(r[2]), "=r"(r[3]) : "r"(addr));
}
__device__ __forceinline__ void mma_f16(float* c, const uint32_t* a, const uint32_t* b) {
    asm volatile(
        "mma.sync.aligned.m16n8k16.row.col.f32.f16.f16.f32 "
        "{%0,%1,%2,%3}, {%4,%5,%6,%7}, {%8,%9}, {%0,%1,%2,%3};"
        : "+f"(c[0]), "+f"(c[1]), "+f"(c[2]), "+f"(c[3])
        : "r"(a[0]), "r"(a[1]), "r"(a[2]), "r"(a[3]), "r"(b[0]), "r"(b[1]));
}

// ---------------------------------------------------------------------------
// fp16 tensor-core GEMM-NT, 3-stage cp.async pipeline:
// C[m,n] = scale * sum_k A[m,k] * B[n,k];  A:[M,K], B:[N,K] half, K-major.
// causal: skip tiles bx>by.  klimit: K limited to (by+1)*BMH (PV causal).
// out_mode: 0 = float C, 1 = half C, 2 = half transposed into Vt [b][d][t].
// ---------------------------------------------------------------------------
__global__ __launch_bounds__(256, 2)
void gemm_h16(const __half* __restrict__ A, const __half* __restrict__ B,
              void* __restrict__ Cv, int N, int K, float scale,
              long long sA, long long sB, long long sC,
              int causal, int klimit, int out_mode)
{
    if (causal && (int)blockIdx.x > (int)blockIdx.y) return;

    extern __shared__ __half sm[];
    const int tid  = threadIdx.x;
    const int lane = tid & 31;
    const int w    = tid >> 5;
    const int wR = w >> 2, wC = w & 3;       // 2 x 4 warps
    const int gid = lane >> 2, tig = lane & 3;
    const int mb = wR * 64, nb = wC * 32;

    const __half* Ab = A + (size_t)blockIdx.z * sA + (size_t)blockIdx.y * BMH * K;
    const __half* Bb = B + (size_t)blockIdx.z * sB + (size_t)blockIdx.x * BNH * K;

    const int T = klimit ? (int)(blockIdx.y + 1) * (BMH / BKH) : K / BKH;

    const int ldr = tid >> 3, ldc = tid & 7;   // loader: row, 16B chunk
    const uint32_t sm0 = smem_u32(sm);

    auto load_tile = [&](int t) {
        const int buf = t % STAGES;
        const uint32_t as = sm0 + buf * 2 * TILEH * 2;
        const uint32_t bs = as + TILEH * 2;
        const int k0 = t * BKH;
        const uint32_t off = (uint32_t)ldr * SKB + ldc * 16;
        const __half* asrc = Ab + (size_t)ldr * K + k0 + ldc * 8;
        const __half* bsrc = Bb + (size_t)ldr * K + k0 + ldc * 8;
        #pragma unroll
        for (int i = 0; i < 4; i++) {
            cp16s(as + off + i * 32 * SKB, asrc + (size_t)32 * i * K);
            cp16s(bs + off + i * 32 * SKB, bsrc + (size_t)32 * i * K);
        }
        cp_commit();
    };

    float acc[4][4][4];
    #pragma unroll
    for (int i = 0; i < 4; i++)
        #pragma unroll
        for (int j = 0; j < 4; j++)
            #pragma unroll
            for (int r = 0; r < 4; r++) acc[i][j][r] = 0.f;

    load_tile(0);
    load_tile(1);

    // ldmatrix lane addresses
    // A: row mb+(lane&15), k-half 8*(lane>>4)
    const uint32_t a_lane_off = (uint32_t)(mb + (lane & 15)) * SKB
                              + (uint32_t)(lane >> 4) * 16;
    // B: lanes 0-7 rows nb..+7 @k, 8-15 rows nb..+7 @k+8, 16-23 nb+8..+15 @k, 24-31 @k+8
    const uint32_t b_lane_off = (uint32_t)(nb + (lane & 7) + ((lane >> 4) << 3)) * SKB
                              + (uint32_t)((lane >> 3) & 1) * 16;

    for (int u = 0; u < T; u++) {
        if (u + 1 < T) cp_wait<1>(); else cp_wait<0>();
        __syncthreads();
        if (u + 2 < T) load_tile(u + 2);

        const int buf = u % STAGES;
        const uint32_t as = sm0 + buf * 2 * TILEH * 2;
        const uint32_t bs = as + TILEH * 2;

        #pragma unroll
        for (int ks = 0; ks < 4; ks++) {
            const int kk = ks * 16;
            uint32_t a[4][4], b[4][2];
            #pragma unroll
            for (int mf = 0; mf < 4; mf++)
                ldm_x4(a[mf], as + a_lane_off + (uint32_t)(mf * 16) * SKB + kk * 2);
            {
                uint32_t r0[4], r1[4];
                ldm_x4(r0, bs + b_lane_off + kk * 2);
                ldm_x4(r1, bs + b_lane_off + 16u * SKB + kk * 2);
                b[0][0] = r0[0]; b[0][1] = r0[1]; b[1][0] = r0[2]; b[1][1] = r0[3];
                b[2][0] = r1[0]; b[2][1] = r1[1]; b[3][0] = r1[2]; b[3][1] = r1[3];
            }
            #pragma unroll
            for (int mf = 0; mf < 4; mf++)
                #pragma unroll
                for (int nf = 0; nf < 4; nf++)
                    mma_f16(acc[mf][nf], a[mf], b[nf]);
        }
    }

    // ---------------- epilogue ----------------
    if (out_mode == 0) {
        float* Cb = (float*)Cv + (size_t)blockIdx.z * sC;
        #pragma unroll
        for (int mf = 0; mf < 4; mf++) {
            int row = blockIdx.y * BMH + mb + mf * 16 + gid;
            #pragma unroll
            for (int nf = 0; nf < 4; nf++) {
                int col = blockIdx.x * BNH + nb + nf * 8 + tig * 2;
                *(float2*)&Cb[(size_t)row * N + col] =
                    make_float2(acc[mf][nf][0] * scale, acc[mf][nf][1] * scale);
                *(float2*)&Cb[(size_t)(row + 8) * N + col] =
                    make_float2(acc[mf][nf][2] * scale, acc[mf][nf][3] * scale);
            }
        }
    } else if (out_mode == 1) {
        __half* Cb = (__half*)Cv + (size_t)blockIdx.z * sC;
        #pragma unroll
        for (int mf = 0; mf < 4; mf++) {
            int row = blockIdx.y * BMH + mb + mf * 16 + gid;
            #pragma unroll
            for (int nf = 0; nf < 4; nf++) {
                int col = blockIdx.x * BNH + nb + nf * 8 + tig * 2;
                *(__half2*)&Cb[(size_t)row * N + col] =
                    __floats2half2_rn(acc[mf][nf][0] * scale, acc[mf][nf][1] * scale);
                *(__half2*)&Cb[(size_t)(row + 8) * N + col] =
                    __floats2half2_rn(acc[mf][nf][2] * scale, acc[mf][nf][3] * scale);
            }
        }
    } else {
        // transposed half output into Vt[b][d][t]; tile rows are tokens,
        // tile cols are d. Stage [col][row] in smem, then coalesced rows out.
        __syncthreads();   // all warps done reading operand tiles
        #define TSD 136
        __half* ts = sm;
        #pragma unroll
        for (int mf = 0; mf < 4; mf++) {
            int row = mb + mf * 16 + gid;
            #pragma unroll
            for (int nf = 0; nf < 4; nf++) {
                int col = nb + nf * 8 + tig * 2;
                ts[(col)     * TSD + row]     = __float2half_rn(acc[mf][nf][0]);
                ts[(col + 1) * TSD + row]     = __float2half_rn(acc[mf][nf][1]);
                ts[(col)     * TSD + row + 8] = __float2half_rn(acc[mf][nf][2]);
                ts[(col + 1) * TSD + row + 8] = __float2half_rn(acc[mf][nf][3]);
            }
        }
        __syncthreads();
        __half* Vt = (__half*)Cv;
        const int row0 = blockIdx.y * BMH;          // global token base
        const int bz   = row0 >> 11;                // batch
        const int t0   = row0 & (NSEQ - 1);
        const int d    = tid >> 1;                  // 0..127 local d
        const int mh   = (tid & 1) * 64;            // half-row chunk
        __half* dst = Vt + (size_t)bz * BDIM * NSEQ
                    + (size_t)(blockIdx.x * BNH + d) * NSEQ + t0 + mh;
        const __half* src = ts + d * TSD + mh;
        #pragma unroll
        for (int i = 0; i < 8; i++)
            *(uint4*)(dst + i * 8) = *(const uint4*)(src + i * 8);
        #undef TSD
    }
}

// ---------------------------------------------------------------------------
// float -> half conversions: x (big) and the 3 weight matrices (one launch)
// ---------------------------------------------------------------------------
__global__ void cvt_h_kernel(const float* __restrict__ in, __half* __restrict__ out,
                             long long n)
{
    long long i = (long long)blockIdx.x * blockDim.x + threadIdx.x;
    long long stride = (long long)gridDim.x * blockDim.x;
    for (; i < n; i += stride)
        out[i] = __float2half_rn(in[i]);
}

__global__ void cvt3_h_kernel(const float* __restrict__ w0, __half* __restrict__ o0,
                              const float* __restrict__ w1, __half* __restrict__ o1,
                              const float* __restrict__ w2, __half* __restrict__ o2,
                              long long n)
{
    const float* in  = (blockIdx.y == 0) ? w0 : (blockIdx.y == 1) ? w1 : w2;
    __half*      out = (blockIdx.y == 0) ? o0 : (blockIdx.y == 1) ? o1 : o2;
    long long i = (long long)blockIdx.x * blockDim.x + threadIdx.x;
    long long stride = (long long)gridDim.x * blockDim.x;
    for (; i < n; i += stride)
        out[i] = __float2half_rn(in[i]);
}

// ---------------------------------------------------------------------------
// Row softmax over causal prefix: fp32 scores in, half probs out.
// Zero-fills P to the next 128 boundary for the PV k-limit.
// ---------------------------------------------------------------------------
__global__ __launch_bounds__(256)
void softmax_kernel(const float* __restrict__ S, __half* __restrict__ P)
{
    __shared__ float buf[NSEQ];
    __shared__ float red[256];

    const int tid = threadIdx.x;
    const int row = blockIdx.x;
    const int b   = row >> 11;
    const int q   = row & (NSEQ - 1);
    const float* srow = S + ((size_t)b * NSEQ + q) * NSEQ;
    __half*      prow = P + ((size_t)b * NSEQ + q) * NSEQ;
    const int len = q + 1;

    float m = -INFINITY;
    for (int j = tid; j < len; j += 256) {
        float v = srow[j];
        buf[j] = v;
        m = fmaxf(m, v);
    }
    red[tid] = m;
    __syncthreads();
    #pragma unroll
    for (int s = 128; s > 0; s >>= 1) {
        if (tid < s) red[tid] = fmaxf(red[tid], red[tid + s]);
        __syncthreads();
    }
    m = red[0];
    __syncthreads();

    float sum = 0.f;
    for (int j = tid; j < len; j += 256) {
        float e = __expf(buf[j] - m);
        buf[j] = e;
        sum += e;
    }
    red[tid] = sum;
    __syncthreads();
    #pragma unroll
    for (int s = 128; s > 0; s >>= 1) {
        if (tid < s) red[tid] += red[tid + s];
        __syncthreads();
    }
    const float inv = 1.f / red[0];

    for (int j = tid; j < len; j += 256)
        prow[j] = __float2half_rn(buf[j] * inv);

    const int zend = ((q >> 7) + 1) << 7;
    for (int j = len + tid; j < zend; j += 256) prow[j] = __float2half_rn(0.f);
}

// ---------------------------------------------------------------------------
extern "C" void kernel_launch(void* const* d_in, const int* in_sizes, int n_in,
                              void* d_out, int out_size)
{
    const float* x  = (const float*)d_in[0];
    const float* Wq = (const float*)d_in[1];
    const float* Wk = (const float*)d_in[2];
    const float* Wv = (const float*)d_in[3];
    float* out = (float*)d_out;

    __half *Xh, *Wqh, *Wkh, *Wvh, *Qh, *Kh, *Vth, *P;
    float* S;
    cudaGetSymbolAddress((void**)&Xh,  g_Xh);
    cudaGetSymbolAddress((void**)&Wqh, g_Wqh);
    cudaGetSymbolAddress((void**)&Wkh, g_Wkh);
    cudaGetSymbolAddress((void**)&Wvh, g_Wvh);
    cudaGetSymbolAddress((void**)&Qh,  g_Qh);
    cudaGetSymbolAddress((void**)&Kh,  g_Kh);
    cudaGetSymbolAddress((void**)&Vth, g_Vth);
    cudaGetSymbolAddress((void**)&S,   g_S);
    cudaGetSymbolAddress((void**)&P,   g_P);

    static int attr_set = 0;
    if (!attr_set) {
        cudaFuncSetAttribute(gemm_h16, cudaFuncAttributeMaxDynamicSharedMemorySize, GEMM_SMEM);
        attr_set = 1;
    }

    // 0) inputs -> half
    cvt_h_kernel<<<1024, 256>>>(x, Xh, (long long)MTOT * BDIM);
    cvt3_h_kernel<<<dim3(512, 3), 256>>>(Wq, Wqh, Wk, Wkh, Wv, Wvh,
                                         (long long)BDIM * BDIM);

    // 1) QKV projections (V written transposed into Vt)
    dim3 gproj(BDIM / BNH, MTOT / BMH, 1);
    gemm_h16<<<gproj, 256, GEMM_SMEM>>>(Xh, Wqh, Qh,  BDIM, BDIM, 1.f, 0, 0, 0, 0, 0, 1);
    gemm_h16<<<gproj, 256, GEMM_SMEM>>>(Xh, Wkh, Kh,  BDIM, BDIM, 1.f, 0, 0, 0, 0, 0, 1);
    gemm_h16<<<gproj, 256, GEMM_SMEM>>>(Xh, Wvh, Vth, BDIM, BDIM, 1.f, 0, 0, 0, 0, 0, 2);

    // 2) Scores: S = Q K^T / 32 (fp32 out), causal tile skip
    dim3 gs(NSEQ / BNH, NSEQ / BMH, NB);
    gemm_h16<<<gs, 256, GEMM_SMEM>>>(Qh, Kh, S, NSEQ, BDIM, 0.03125f,
                                     (long long)NSEQ * BDIM, (long long)NSEQ * BDIM,
                                     (long long)NSEQ * NSEQ, 1, 0, 0);

    // 3) causal softmax: fp32 scores -> half probs (zero-filled to 128)
    softmax_kernel<<<NB * NSEQ, 256>>>(S, P);

    // 4) O = P Vt^T with causal k-limit (fp32 out)
    dim3 go(BDIM / BNH, NSEQ / BMH, NB);
    gemm_h16<<<go, 256, GEMM_SMEM>>>(P, Vth, out, BDIM, NSEQ, 1.f,
                                     (long long)NSEQ * NSEQ, (long long)BDIM * NSEQ,
                                     (long long)NSEQ * BDIM, 0, 1, 0);
}

// round 12
// speedup vs baseline: 7.3904x; 1.0931x over previous
#include <cuda_runtime.h>
#include <cuda_fp16.h>
#include <math.h>
#include <stdint.h>

// Problem dims
#define NB    4
#define NSEQ  2048
#define BDIM  1024
#define MTOT  (NB * NSEQ)   // 8192

// GEMM tiling (fp16 mma.sync m16n8k16)
#define BMH 128
#define BNH 128
#define BKH 64
#define SKH 72                 // halves/row (64 + 8 pad) -> 144B stride
#define SKB (SKH * 2)          // row stride bytes
#define TILEH (BMH * SKH)      // halves per operand tile
#define STAGES 3
#define GEMM_SMEM (STAGES * 2 * TILEH * 2)   // 110592 B

// Scratch (device globals: allocation-free, per harness rules)
__device__ __half g_Xh [(size_t)MTOT * BDIM];
__device__ __half g_Wqh[(size_t)BDIM * BDIM];
__device__ __half g_Wkh[(size_t)BDIM * BDIM];
__device__ __half g_Wvh[(size_t)BDIM * BDIM];
__device__ __half g_Qh [(size_t)MTOT * BDIM];
__device__ __half g_Kh [(size_t)MTOT * BDIM];
__device__ __half g_Vth[(size_t)MTOT * BDIM];   // [b][d][t]
__device__ float  g_S  [(size_t)NB * NSEQ * NSEQ];
__device__ __half g_P  [(size_t)NB * NSEQ * NSEQ];

// ---------------- PTX helpers ----------------
__device__ __forceinline__ uint32_t smem_u32(const void* p) {
    uint32_t a;
    asm("{ .reg .u64 t; cvta.to.shared.u64 t, %1; cvt.u32.u64 %0, t; }" : "=r"(a) : "l"(p));
    return a;
}
__device__ __forceinline__ void cp16s(uint32_t dst, const void* src) {
    asm volatile("cp.async.cg.shared.global [%0], [%1], 16;" :: "r"(dst), "l"(src));
}
__device__ __forceinline__ void cp_commit() { asm volatile("cp.async.commit_group;"); }
template <int N>
__device__ __forceinline__ void cp_wait() { asm volatile("cp.async.wait_group %0;" :: "n"(N)); }

__device__ __forceinline__ void ldm_x4(uint32_t* r, uint32_t addr) {
    asm volatile("ldmatrix.sync.aligned.m8n8.x4.shared.b16 {%0,%1,%2,%3}, [%4];"
                 : "=r"(r[0]), "=r"(r[1]), "=r"(r[2]), "=r"(r[3]) : "r"(addr));
}
__device__ __forceinline__ void mma_f16(float* c, const uint32_t* a, const uint32_t* b) {
    asm volatile(
        "mma.sync.aligned.m16n8k16.row.col.f32.f16.f16.f32 "
        "{%0,%1,%2,%3}, {%4,%5,%6,%7}, {%8,%9}, {%0,%1,%2,%3};"
        : "+f"(c[0]), "+f"(c[1]), "+f"(c[2]), "+f"(c[3])
        : "r"(a[0]), "r"(a[1]), "r"(a[2]), "r"(a[3]), "r"(b[0]), "r"(b[1]));
}

// ---------------------------------------------------------------------------
// Shared 3-stage cp.async mainloop: acc += A_tile * B_tile^T over T k-tiles.
// ---------------------------------------------------------------------------
__device__ __forceinline__ void gemm_mainloop(
    const __half* __restrict__ Ab, const __half* __restrict__ Bb,
    int K, int T, uint32_t sm0, int tid, uint32_t a_lane_off, uint32_t b_lane_off,
    float acc[4][4][4])
{
    const int ldr = tid >> 3, ldc = tid & 7;   // loader: row, 16B chunk

    auto load_tile = [&](int t) {
        const int buf = t % STAGES;
        const uint32_t as = sm0 + buf * 2 * TILEH * 2;
        const uint32_t bs = as + TILEH * 2;
        const int k0 = t * BKH;
        const uint32_t off = (uint32_t)ldr * SKB + ldc * 16;
        const __half* asrc = Ab + (size_t)ldr * K + k0 + ldc * 8;
        const __half* bsrc = Bb + (size_t)ldr * K + k0 + ldc * 8;
        #pragma unroll
        for (int i = 0; i < 4; i++) {
            cp16s(as + off + i * 32 * SKB, asrc + (size_t)32 * i * K);
            cp16s(bs + off + i * 32 * SKB, bsrc + (size_t)32 * i * K);
        }
        cp_commit();
    };

    load_tile(0);
    load_tile(1);

    for (int u = 0; u < T; u++) {
        if (u + 1 < T) cp_wait<1>(); else cp_wait<0>();
        __syncthreads();
        if (u + 2 < T) load_tile(u + 2);

        const int buf = u % STAGES;
        const uint32_t as = sm0 + buf * 2 * TILEH * 2;
        const uint32_t bs = as + TILEH * 2;

        #pragma unroll
        for (int ks = 0; ks < 4; ks++) {
            const int kk = ks * 16;
            uint32_t a[4][4], b[4][2];
            #pragma unroll
            for (int mf = 0; mf < 4; mf++)
                ldm_x4(a[mf], as + a_lane_off + (uint32_t)(mf * 16) * SKB + kk * 2);
            {
                uint32_t r0[4], r1[4];
                ldm_x4(r0, bs + b_lane_off + kk * 2);
                ldm_x4(r1, bs + b_lane_off + 16u * SKB + kk * 2);
                b[0][0] = r0[0]; b[0][1] = r0[1]; b[1][0] = r0[2]; b[1][1] = r0[3];
                b[2][0] = r1[0]; b[2][1] = r1[1]; b[3][0] = r1[2]; b[3][1] = r1[3];
            }
            #pragma unroll
            for (int mf = 0; mf < 4; mf++)
                #pragma unroll
                for (int nf = 0; nf < 4; nf++)
                    mma_f16(acc[mf][nf], a[mf], b[nf]);
        }
    }
}

#define GEMM_THREAD_IDS \
    const int tid  = threadIdx.x; \
    const int lane = tid & 31; \
    const int w    = tid >> 5; \
    const int wR = w >> 2, wC = w & 3; \
    const int gid = lane >> 2, tig = lane & 3; \
    const int mb = wR * 64, nb = wC * 32; \
    const uint32_t a_lane_off = (uint32_t)(mb + (lane & 15)) * SKB \
                              + (uint32_t)(lane >> 4) * 16; \
    const uint32_t b_lane_off = (uint32_t)(nb + (lane & 7) + ((lane >> 4) << 3)) * SKB \
                              + (uint32_t)((lane >> 3) & 1) * 16;

#define ACC_INIT \
    float acc[4][4][4]; \
    _Pragma("unroll") for (int i = 0; i < 4; i++) \
        _Pragma("unroll") for (int j = 0; j < 4; j++) \
            _Pragma("unroll") for (int r = 0; r < 4; r++) acc[i][j][r] = 0.f;

// ---------------------------------------------------------------------------
// Fused QKV projection: z=0 -> Q (half), z=1 -> K (half), z=2 -> V written
// transposed into Vt[b][d][t] (half). One launch, grid (8, 64, 3).
// ---------------------------------------------------------------------------
__global__ __launch_bounds__(256, 2)
void gemm_qkv(const __half* __restrict__ X,
              const __half* __restrict__ Wq, const __half* __restrict__ Wk,
              const __half* __restrict__ Wv,
              __half* __restrict__ Q, __half* __restrict__ Ko,
              __half* __restrict__ Vt)
{
    extern __shared__ __half sm[];
    GEMM_THREAD_IDS
    const uint32_t sm0 = smem_u32(sm);

    const int z = blockIdx.z;
    const __half* W = (z == 0) ? Wq : (z == 1) ? Wk : Wv;

    const __half* Ab = X + (size_t)blockIdx.y * BMH * BDIM;
    const __half* Bb = W + (size_t)blockIdx.x * BNH * BDIM;

    ACC_INIT
    gemm_mainloop(Ab, Bb, BDIM, BDIM / BKH, sm0, tid, a_lane_off, b_lane_off, acc);

    if (z < 2) {
        __half* Cb = (z == 0) ? Q : Ko;
        #pragma unroll
        for (int mf = 0; mf < 4; mf++) {
            int row = blockIdx.y * BMH + mb + mf * 16 + gid;
            #pragma unroll
            for (int nf = 0; nf < 4; nf++) {
                int col = blockIdx.x * BNH + nb + nf * 8 + tig * 2;
                *(__half2*)&Cb[(size_t)row * BDIM + col] =
                    __floats2half2_rn(acc[mf][nf][0], acc[mf][nf][1]);
                *(__half2*)&Cb[(size_t)(row + 8) * BDIM + col] =
                    __floats2half2_rn(acc[mf][nf][2], acc[mf][nf][3]);
            }
        }
    } else {
        // stage [d][token] in smem, write Vt rows coalesced
        __syncthreads();
        #define TSD 136
        __half* ts = sm;
        #pragma unroll
        for (int mf = 0; mf < 4; mf++) {
            int row = mb + mf * 16 + gid;
            #pragma unroll
            for (int nf = 0; nf < 4; nf++) {
                int col = nb + nf * 8 + tig * 2;
                ts[(col)     * TSD + row]     = __float2half_rn(acc[mf][nf][0]);
                ts[(col + 1) * TSD + row]     = __float2half_rn(acc[mf][nf][1]);
                ts[(col)     * TSD + row + 8] = __float2half_rn(acc[mf][nf][2]);
                ts[(col + 1) * TSD + row + 8] = __float2half_rn(acc[mf][nf][3]);
            }
        }
        __syncthreads();
        const int row0 = blockIdx.y * BMH;
        const int bz   = row0 >> 11;
        const int t0   = row0 & (NSEQ - 1);
        const int d    = tid >> 1;
        const int mh   = (tid & 1) * 64;
        __half* dst = Vt + (size_t)bz * BDIM * NSEQ
                    + (size_t)(blockIdx.x * BNH + d) * NSEQ + t0 + mh;
        const __half* src = ts + d * TSD + mh;
        #pragma unroll
        for (int i = 0; i < 8; i++)
            *(uint4*)(dst + i * 8) = *(const uint4*)(src + i * 8);
        #undef TSD
    }
}

// ---------------------------------------------------------------------------
// Generic GEMM-NT (scores / PV):
// causal: skip tiles bx>by.  klimit: K limited to (by+1)*BMH.
// C always float.
// ---------------------------------------------------------------------------
__global__ __launch_bounds__(256, 2)
void gemm_h16(const __half* __restrict__ A, const __half* __restrict__ B,
              float* __restrict__ C, int N, int K, float scale,
              long long sA, long long sB, long long sC,
              int causal, int klimit)
{
    if (causal && (int)blockIdx.x > (int)blockIdx.y) return;

    extern __shared__ __half sm[];
    GEMM_THREAD_IDS
    const uint32_t sm0 = smem_u32(sm);

    const __half* Ab = A + (size_t)blockIdx.z * sA + (size_t)blockIdx.y * BMH * K;
    const __half* Bb = B + (size_t)blockIdx.z * sB + (size_t)blockIdx.x * BNH * K;
    const int T = klimit ? (int)(blockIdx.y + 1) * (BMH / BKH) : K / BKH;

    ACC_INIT
    gemm_mainloop(Ab, Bb, K, T, sm0, tid, a_lane_off, b_lane_off, acc);

    float* Cb = C + (size_t)blockIdx.z * sC;
    #pragma unroll
    for (int mf = 0; mf < 4; mf++) {
        int row = blockIdx.y * BMH + mb + mf * 16 + gid;
        #pragma unroll
        for (int nf = 0; nf < 4; nf++) {
            int col = blockIdx.x * BNH + nb + nf * 8 + tig * 2;
            *(float2*)&Cb[(size_t)row * N + col] =
                make_float2(acc[mf][nf][0] * scale, acc[mf][nf][1] * scale);
            *(float2*)&Cb[(size_t)(row + 8) * N + col] =
                make_float2(acc[mf][nf][2] * scale, acc[mf][nf][3] * scale);
        }
    }
}

// ---------------------------------------------------------------------------
// float -> half conversions
// ---------------------------------------------------------------------------
__global__ void cvt_h_kernel(const float* __restrict__ in, __half* __restrict__ out,
                             long long n)
{
    long long i = (long long)blockIdx.x * blockDim.x + threadIdx.x;
    long long stride = (long long)gridDim.x * blockDim.x;
    for (; i < n; i += stride)
        out[i] = __float2half_rn(in[i]);
}

__global__ void cvt3_h_kernel(const float* __restrict__ w0, __half* __restrict__ o0,
                              const float* __restrict__ w1, __half* __restrict__ o1,
                              const float* __restrict__ w2, __half* __restrict__ o2,
                              long long n)
{
    const float* in  = (blockIdx.y == 0) ? w0 : (blockIdx.y == 1) ? w1 : w2;
    __half*      out = (blockIdx.y == 0) ? o0 : (blockIdx.y == 1) ? o1 : o2;
    long long i = (long long)blockIdx.x * blockDim.x + threadIdx.x;
    long long stride = (long long)gridDim.x * blockDim.x;
    for (; i < n; i += stride)
        out[i] = __float2half_rn(in[i]);
}

// ---------------------------------------------------------------------------
// Row softmax over causal prefix, no max pass (scores bounded, |s| << 80):
// exp+sum in one pass (smem-cached), then normalize to half.
// Zero-fills P to the next 128 boundary for the PV k-limit.
// ---------------------------------------------------------------------------
__global__ __launch_bounds__(256)
void softmax_kernel(const float* __restrict__ S, __half* __restrict__ P)
{
    __shared__ float buf[NSEQ];
    __shared__ float wred[8];

    const int tid = threadIdx.x;
    const int row = blockIdx.x;
    const int b   = row >> 11;
    const int q   = row & (NSEQ - 1);
    const float* srow = S + ((size_t)b * NSEQ + q) * NSEQ;
    __half*      prow = P + ((size_t)b * NSEQ + q) * NSEQ;
    const int len = q + 1;

    float sum = 0.f;
    for (int j = tid; j < len; j += 256) {
        float e = __expf(srow[j]);
        buf[j] = e;
        sum += e;
    }
    // warp shuffle reduce, then 8-wide smem reduce
    #pragma unroll
    for (int s = 16; s > 0; s >>= 1)
        sum += __shfl_xor_sync(0xffffffffu, sum, s);
    if ((tid & 31) == 0) wred[tid >> 5] = sum;
    __syncthreads();
    if (tid < 8) {
        float v = wred[tid];
        #pragma unroll
        for (int s = 4; s > 0; s >>= 1)
            v += __shfl_xor_sync(0xffu, v, s);
        if (tid == 0) wred[0] = v;
    }
    __syncthreads();
    const float inv = 1.f / wred[0];

    for (int j = tid; j < len; j += 256)
        prow[j] = __float2half_rn(buf[j] * inv);

    const int zend = ((q >> 7) + 1) << 7;
    for (int j = len + tid; j < zend; j += 256) prow[j] = __float2half_rn(0.f);
}

// ---------------------------------------------------------------------------
extern "C" void kernel_launch(void* const* d_in, const int* in_sizes, int n_in,
                              void* d_out, int out_size)
{
    const float* x  = (const float*)d_in[0];
    const float* Wq = (const float*)d_in[1];
    const float* Wk = (const float*)d_in[2];
    const float* Wv = (const float*)d_in[3];
    float* out = (float*)d_out;

    __half *Xh, *Wqh, *Wkh, *Wvh, *Qh, *Kh, *Vth, *P;
    float* S;
    cudaGetSymbolAddress((void**)&Xh,  g_Xh);
    cudaGetSymbolAddress((void**)&Wqh, g_Wqh);
    cudaGetSymbolAddress((void**)&Wkh, g_Wkh);
    cudaGetSymbolAddress((void**)&Wvh, g_Wvh);
    cudaGetSymbolAddress((void**)&Qh,  g_Qh);
    cudaGetSymbolAddress((void**)&Kh,  g_Kh);
    cudaGetSymbolAddress((void**)&Vth, g_Vth);
    cudaGetSymbolAddress((void**)&S,   g_S);
    cudaGetSymbolAddress((void**)&P,   g_P);

    static int attr_set = 0;
    if (!attr_set) {
        cudaFuncSetAttribute(gemm_qkv, cudaFuncAttributeMaxDynamicSharedMemorySize, GEMM_SMEM);
        cudaFuncSetAttribute(gemm_h16, cudaFuncAttributeMaxDynamicSharedMemorySize, GEMM_SMEM);
        attr_set = 1;
    }

    // 0) inputs -> half
    cvt_h_kernel<<<1024, 256>>>(x, Xh, (long long)MTOT * BDIM);
    cvt3_h_kernel<<<dim3(512, 3), 256>>>(Wq, Wqh, Wk, Wkh, Wv, Wvh,
                                         (long long)BDIM * BDIM);

    // 1) fused QKV projection (one launch; V written transposed)
    dim3 gproj(BDIM / BNH, MTOT / BMH, 3);
    gemm_qkv<<<gproj, 256, GEMM_SMEM>>>(Xh, Wqh, Wkh, Wvh, Qh, Kh, Vth);

    // 2) Scores: S = Q K^T / 32 (fp32 out), causal tile skip
    dim3 gs(NSEQ / BNH, NSEQ / BMH, NB);
    gemm_h16<<<gs, 256, GEMM_SMEM>>>(Qh, Kh, S, NSEQ, BDIM, 0.03125f,
                                     (long long)NSEQ * BDIM, (long long)NSEQ * BDIM,
                                     (long long)NSEQ * NSEQ, 1, 0);

    // 3) causal softmax: fp32 scores -> half probs (zero-filled to 128)
    softmax_kernel<<<NB * NSEQ, 256>>>(S, P);

    // 4) O = P Vt^T with causal k-limit (fp32 out)
    dim3 go(BDIM / BNH, NSEQ / BMH, NB);
    gemm_h16<<<go, 256, GEMM_SMEM>>>(P, Vth, out, BDIM, NSEQ, 1.f,
                                     (long long)NSEQ * NSEQ, (long long)BDIM * NSEQ,
                                     (long long)NSEQ * BDIM, 0, 1);
}

// round 14
// speedup vs baseline: 7.6672x; 1.0375x over previous
#include <cuda_runtime.h>
#include <cuda_fp16.h>
#include <math.h>
#include <stdint.h>

// Problem dims
#define NB    4
#define NSEQ  2048
#define BDIM  1024
#define MTOT  (NB * NSEQ)   // 8192

// GEMM tiling (fp16 mma.sync m16n8k16)
#define BMH 128
#define BNH 128
#define BKH 64
#define SKH 72                 // halves/row (64 + 8 pad) -> 144B stride
#define SKB (SKH * 2)          // row stride bytes
#define TILEH (BMH * SKH)      // halves per operand tile
#define STAGES 3
#define GEMM_SMEM (STAGES * 2 * TILEH * 2)   // 110592 B

// Scratch (device globals: allocation-free, per harness rules)
__device__ __half g_Xh [(size_t)MTOT * BDIM];
__device__ __half g_Wqh[(size_t)BDIM * BDIM];
__device__ __half g_Wkh[(size_t)BDIM * BDIM];
__device__ __half g_Wvh[(size_t)BDIM * BDIM];
__device__ __half g_Qh [(size_t)MTOT * BDIM];
__device__ __half g_Kh [(size_t)MTOT * BDIM];
__device__ __half g_Vth[(size_t)MTOT * BDIM];   // [b][d][t]
__device__ __half g_P  [(size_t)NB * NSEQ * NSEQ];  // unnormalized exp(S)
__device__ float  g_Spart[(size_t)16 * MTOT];   // per-kblock row partial sums
__device__ float  g_inv[(size_t)MTOT];          // 1/rowsum

// ---------------- PTX helpers ----------------
__device__ __forceinline__ uint32_t smem_u32(const void* p) {
    uint32_t a;
    asm("{ .reg .u64 t; cvta.to.shared.u64 t, %1; cvt.u32.u64 %0, t; }" : "=r"(a) : "l"(p));
    return a;
}
__device__ __forceinline__ void cp16s(uint32_t dst, const void* src) {
    asm volatile("cp.async.cg.shared.global [%0], [%1], 16;" :: "r"(dst), "l"(src));
}
__device__ __forceinline__ void cp_commit() { asm volatile("cp.async.commit_group;"); }
template <int N>
__device__ __forceinline__ void cp_wait() { asm volatile("cp.async.wait_group %0;" :: "n"(N)); }

__device__ __forceinline__ void ldm_x4(uint32_t* r, uint32_t addr) {
    asm volatile("ldmatrix.sync.aligned.m8n8.x4.shared.b16 {%0,%1,%2,%3}, [%4];"
                 : "=r"(r[0]), "=r"(r[1]), "=r"(r[2]), "=r"(r[3]) : "r"(addr));
}
__device__ __forceinline__ void mma_f16(float* c, const uint32_t* a, const uint32_t* b) {
    asm volatile(
        "mma.sync.aligned.m16n8k16.row.col.f32.f16.f16.f32 "
        "{%0,%1,%2,%3}, {%4,%5,%6,%7}, {%8,%9}, {%0,%1,%2,%3};"
        : "+f"(c[0]), "+f"(c[1]), "+f"(c[2]), "+f"(c[3])
        : "r"(a[0]), "r"(a[1]), "r"(a[2]), "r"(a[3]), "r"(b[0]), "r"(b[1]));
}

// ---------------------------------------------------------------------------
// Shared 3-stage cp.async mainloop: acc += A_tile * B_tile^T over T k-tiles.
// ---------------------------------------------------------------------------
__device__ __forceinline__ void gemm_mainloop(
    const __half* __restrict__ Ab, const __half* __restrict__ Bb,
    int K, int T, uint32_t sm0, int tid, uint32_t a_lane_off, uint32_t b_lane_off,
    float acc[4][4][4])
{
    const int ldr = tid >> 3, ldc = tid & 7;   // loader: row, 16B chunk

    auto load_tile = [&](int t) {
        const int buf = t % STAGES;
        const uint32_t as = sm0 + buf * 2 * TILEH * 2;
        const uint32_t bs = as + TILEH * 2;
        const int k0 = t * BKH;
        const uint32_t off = (uint32_t)ldr * SKB + ldc * 16;
        const __half* asrc = Ab + (size_t)ldr * K + k0 + ldc * 8;
        const __half* bsrc = Bb + (size_t)ldr * K + k0 + ldc * 8;
        #pragma unroll
        for (int i = 0; i < 4; i++) {
            cp16s(as + off + i * 32 * SKB, asrc + (size_t)32 * i * K);
            cp16s(bs + off + i * 32 * SKB, bsrc + (size_t)32 * i * K);
        }
        cp_commit();
    };

    load_tile(0);
    load_tile(1);

    for (int u = 0; u < T; u++) {
        if (u + 1 < T) cp_wait<1>(); else cp_wait<0>();
        __syncthreads();
        if (u + 2 < T) load_tile(u + 2);

        const int buf = u % STAGES;
        const uint32_t as = sm0 + buf * 2 * TILEH * 2;
        const uint32_t bs = as + TILEH * 2;

        #pragma unroll
        for (int ks = 0; ks < 4; ks++) {
            const int kk = ks * 16;
            uint32_t a[4][4], b[4][2];
            #pragma unroll
            for (int mf = 0; mf < 4; mf++)
                ldm_x4(a[mf], as + a_lane_off + (uint32_t)(mf * 16) * SKB + kk * 2);
            {
                uint32_t r0[4], r1[4];
                ldm_x4(r0, bs + b_lane_off + kk * 2);
                ldm_x4(r1, bs + b_lane_off + 16u * SKB + kk * 2);
                b[0][0] = r0[0]; b[0][1] = r0[1]; b[1][0] = r0[2]; b[1][1] = r0[3];
                b[2][0] = r1[0]; b[2][1] = r1[1]; b[3][0] = r1[2]; b[3][1] = r1[3];
            }
            #pragma unroll
            for (int mf = 0; mf < 4; mf++)
                #pragma unroll
                for (int nf = 0; nf < 4; nf++)
                    mma_f16(acc[mf][nf], a[mf], b[nf]);
        }
    }
}

#define GEMM_THREAD_IDS \
    const int tid  = threadIdx.x; \
    const int lane = tid & 31; \
    const int w    = tid >> 5; \
    const int wR = w >> 2, wC = w & 3; \
    const int gid = lane >> 2, tig = lane & 3; \
    const int mb = wR * 64, nb = wC * 32; \
    const uint32_t a_lane_off = (uint32_t)(mb + (lane & 15)) * SKB \
                              + (uint32_t)(lane >> 4) * 16; \
    const uint32_t b_lane_off = (uint32_t)(nb + (lane & 7) + ((lane >> 4) << 3)) * SKB \
                              + (uint32_t)((lane >> 3) & 1) * 16;

#define ACC_INIT \
    float acc[4][4][4]; \
    _Pragma("unroll") for (int i = 0; i < 4; i++) \
        _Pragma("unroll") for (int j = 0; j < 4; j++) \
            _Pragma("unroll") for (int r = 0; r < 4; r++) acc[i][j][r] = 0.f;

// ---------------------------------------------------------------------------
// Fused QKV projection: z=0 -> Q, z=1 -> K, z=2 -> V transposed into Vt.
// ---------------------------------------------------------------------------
__global__ __launch_bounds__(256, 2)
void gemm_qkv(const __half* __restrict__ X,
              const __half* __restrict__ Wq, const __half* __restrict__ Wk,
              const __half* __restrict__ Wv,
              __half* __restrict__ Q, __half* __restrict__ Ko,
              __half* __restrict__ Vt)
{
    extern __shared__ __half sm[];
    GEMM_THREAD_IDS
    const uint32_t sm0 = smem_u32(sm);

    const int z = blockIdx.z;
    const __half* W = (z == 0) ? Wq : (z == 1) ? Wk : Wv;

    const __half* Ab = X + (size_t)blockIdx.y * BMH * BDIM;
    const __half* Bb = W + (size_t)blockIdx.x * BNH * BDIM;

    ACC_INIT
    gemm_mainloop(Ab, Bb, BDIM, BDIM / BKH, sm0, tid, a_lane_off, b_lane_off, acc);

    if (z < 2) {
        __half* Cb = (z == 0) ? Q : Ko;
        #pragma unroll
        for (int mf = 0; mf < 4; mf++) {
            int row = blockIdx.y * BMH + mb + mf * 16 + gid;
            #pragma unroll
            for (int nf = 0; nf < 4; nf++) {
                int col = blockIdx.x * BNH + nb + nf * 8 + tig * 2;
                *(__half2*)&Cb[(size_t)row * BDIM + col] =
                    __floats2half2_rn(acc[mf][nf][0], acc[mf][nf][1]);
                *(__half2*)&Cb[(size_t)(row + 8) * BDIM + col] =
                    __floats2half2_rn(acc[mf][nf][2], acc[mf][nf][3]);
            }
        }
    } else {
        __syncthreads();
        #define TSD 136
        __half* ts = sm;
        #pragma unroll
        for (int mf = 0; mf < 4; mf++) {
            int row = mb + mf * 16 + gid;
            #pragma unroll
            for (int nf = 0; nf < 4; nf++) {
                int col = nb + nf * 8 + tig * 2;
                ts[(col)     * TSD + row]     = __float2half_rn(acc[mf][nf][0]);
                ts[(col + 1) * TSD + row]     = __float2half_rn(acc[mf][nf][1]);
                ts[(col)     * TSD + row + 8] = __float2half_rn(acc[mf][nf][2]);
                ts[(col + 1) * TSD + row + 8] = __float2half_rn(acc[mf][nf][3]);
            }
        }
        __syncthreads();
        const int row0 = blockIdx.y * BMH;
        const int bz   = row0 >> 11;
        const int t0   = row0 & (NSEQ - 1);
        const int d    = tid >> 1;
        const int mh   = (tid & 1) * 64;
        __half* dst = Vt + (size_t)bz * BDIM * NSEQ
                    + (size_t)(blockIdx.x * BNH + d) * NSEQ + t0 + mh;
        const __half* src = ts + d * TSD + mh;
        #pragma unroll
        for (int i = 0; i < 8; i++)
            *(uint4*)(dst + i * 8) = *(const uint4*)(src + i * 8);
        #undef TSD
    }
}

// ---------------------------------------------------------------------------
// Scores + fused exp + causal mask + deterministic row partial sums.
// Writes unnormalized P (half). Descending-y remap (big rows first).
// ---------------------------------------------------------------------------
__global__ __launch_bounds__(256, 2)
void gemm_scores(const __half* __restrict__ Q, const __half* __restrict__ Kh,
                 __half* __restrict__ P, float* __restrict__ Spart)
{
    const int by = (int)gridDim.y - 1 - (int)blockIdx.y;   // big rows first
    const int bx = blockIdx.x;
    if (bx > by) return;

    extern __shared__ __half sm[];
    GEMM_THREAD_IDS
    const uint32_t sm0 = smem_u32(sm);
    const int z = blockIdx.z;

    const __half* Ab = Q  + (size_t)z * NSEQ * BDIM + (size_t)by * BMH * BDIM;
    const __half* Bb = Kh + (size_t)z * NSEQ * BDIM + (size_t)bx * BNH * BDIM;

    ACC_INIT
    gemm_mainloop(Ab, Bb, BDIM, BDIM / BKH, sm0, tid, a_lane_off, b_lane_off, acc);

    // epilogue: exp(s/32), mask, write half P, reduce row sums
    __syncthreads();
    float* rs = (float*)sm;                  // [128][4]
    const bool diag = (bx == by);
    __half* Pb = P + (size_t)z * NSEQ * NSEQ;
    const float SC = 0.03125f;

    #pragma unroll
    for (int mf = 0; mf < 4; mf++) {
        const int rl = mb + mf * 16 + gid;   // local row
        const int r0 = by * BMH + rl;        // row in batch
        float sA = 0.f, sB = 0.f;
        #pragma unroll
        for (int nf = 0; nf < 4; nf++) {
            int col = bx * BNH + nb + nf * 8 + tig * 2;
            float e0 = __expf(acc[mf][nf][0] * SC);
            float e1 = __expf(acc[mf][nf][1] * SC);
            float e2 = __expf(acc[mf][nf][2] * SC);
            float e3 = __expf(acc[mf][nf][3] * SC);
            if (diag) {
                if (col     > r0)     e0 = 0.f;
                if (col + 1 > r0)     e1 = 0.f;
                if (col     > r0 + 8) e2 = 0.f;
                if (col + 1 > r0 + 8) e3 = 0.f;
            }
            *(__half2*)&Pb[(size_t)r0 * NSEQ + col]       = __floats2half2_rn(e0, e1);
            *(__half2*)&Pb[(size_t)(r0 + 8) * NSEQ + col] = __floats2half2_rn(e2, e3);
            sA += e0 + e1;
            sB += e2 + e3;
        }
        sA += __shfl_xor_sync(0xffffffffu, sA, 1);
        sA += __shfl_xor_sync(0xffffffffu, sA, 2);
        sB += __shfl_xor_sync(0xffffffffu, sB, 1);
        sB += __shfl_xor_sync(0xffffffffu, sB, 2);
        if (tig == 0) {
            rs[rl * 4 + wC]       = sA;
            rs[(rl + 8) * 4 + wC] = sB;
        }
    }
    __syncthreads();
    if (tid < 128) {
        float t = rs[tid * 4] + rs[tid * 4 + 1] + rs[tid * 4 + 2] + rs[tid * 4 + 3];
        Spart[(size_t)bx * MTOT + (size_t)z * NSEQ + by * BMH + tid] = t;
    }
}

// ---------------------------------------------------------------------------
// Fold partial sums -> inv[row] (deterministic, fixed order)
// ---------------------------------------------------------------------------
__global__ void sumrows_kernel(const float* __restrict__ Spart,
                               float* __restrict__ inv)
{
    int r = blockIdx.x * 256 + threadIdx.x;     // 0..MTOT-1
    int q = r & (NSEQ - 1);
    int nblk = (q >> 7) + 1;
    float s = 0.f;
    for (int bx = 0; bx < nblk; bx++)
        s += Spart[(size_t)bx * MTOT + r];
    inv[r] = 1.f / s;
}

// ---------------------------------------------------------------------------
// PV: O[q,d] = inv[q] * sum_j P[q,j]*Vt[d,j], causal k-limit, big rows first.
// ---------------------------------------------------------------------------
__global__ __launch_bounds__(256, 2)
void gemm_pv(const __half* __restrict__ P, const __half* __restrict__ Vt,
             const float* __restrict__ inv, float* __restrict__ O)
{
    const int by = (int)gridDim.y - 1 - (int)blockIdx.y;   // big rows first
    extern __shared__ __half sm[];
    GEMM_THREAD_IDS
    const uint32_t sm0 = smem_u32(sm);
    const int z = blockIdx.z;

    const __half* Ab = P  + (size_t)z * NSEQ * NSEQ + (size_t)by * BMH * NSEQ;
    const __half* Bb = Vt + (size_t)z * BDIM * NSEQ + (size_t)blockIdx.x * BNH * NSEQ;
    const int T = (by + 1) * (BMH / BKH);

    ACC_INIT
    gemm_mainloop(Ab, Bb, NSEQ, T, sm0, tid, a_lane_off, b_lane_off, acc);

    float* Cb = O + (size_t)z * NSEQ * BDIM;
    #pragma unroll
    for (int mf = 0; mf < 4; mf++) {
        int row = by * BMH + mb + mf * 16 + gid;
        float iv0 = inv[(size_t)z * NSEQ + row];
        float iv1 = inv[(size_t)z * NSEQ + row + 8];
        #pragma unroll
        for (int nf = 0; nf < 4; nf++) {
            int col = blockIdx.x * BNH + nb + nf * 8 + tig * 2;
            *(float2*)&Cb[(size_t)row * BDIM + col] =
                make_float2(acc[mf][nf][0] * iv0, acc[mf][nf][1] * iv0);
            *(float2*)&Cb[(size_t)(row + 8) * BDIM + col] =
                make_float2(acc[mf][nf][2] * iv1, acc[mf][nf][3] * iv1);
        }
    }
}

// ---------------------------------------------------------------------------
// float -> half conversions
// ---------------------------------------------------------------------------
__global__ void cvt_h_kernel(const float* __restrict__ in, __half* __restrict__ out,
                             long long n)
{
    long long i = (long long)blockIdx.x * blockDim.x + threadIdx.x;
    long long stride = (long long)gridDim.x * blockDim.x;
    for (; i < n; i += stride)
        out[i] = __float2half_rn(in[i]);
}

__global__ void cvt3_h_kernel(const float* __restrict__ w0, __half* __restrict__ o0,
                              const float* __restrict__ w1, __half* __restrict__ o1,
                              const float* __restrict__ w2, __half* __restrict__ o2,
                              long long n)
{
    const float* in  = (blockIdx.y == 0) ? w0 : (blockIdx.y == 1) ? w1 : w2;
    __half*      out = (blockIdx.y == 0) ? o0 : (blockIdx.y == 1) ? o1 : o2;
    long long i = (long long)blockIdx.x * blockDim.x + threadIdx.x;
    long long stride = (long long)gridDim.x * blockDim.x;
    for (; i < n; i += stride)
        out[i] = __float2half_rn(in[i]);
}

// ---------------------------------------------------------------------------
extern "C" void kernel_launch(void* const* d_in, const int* in_sizes, int n_in,
                              void* d_out, int out_size)
{
    const float* x  = (const float*)d_in[0];
    const float* Wq = (const float*)d_in[1];
    const float* Wk = (const float*)d_in[2];
    const float* Wv = (const float*)d_in[3];
    float* out = (float*)d_out;

    __half *Xh, *Wqh, *Wkh, *Wvh, *Qh, *Kh, *Vth, *P;
    float *Spart, *inv;
    cudaGetSymbolAddress((void**)&Xh,   g_Xh);
    cudaGetSymbolAddress((void**)&Wqh,  g_Wqh);
    cudaGetSymbolAddress((void**)&Wkh,  g_Wkh);
    cudaGetSymbolAddress((void**)&Wvh,  g_Wvh);
    cudaGetSymbolAddress((void**)&Qh,   g_Qh);
    cudaGetSymbolAddress((void**)&Kh,   g_Kh);
    cudaGetSymbolAddress((void**)&Vth,  g_Vth);
    cudaGetSymbolAddress((void**)&P,    g_P);
    cudaGetSymbolAddress((void**)&Spart, g_Spart);
    cudaGetSymbolAddress((void**)&inv,  g_inv);

    static int attr_set = 0;
    if (!attr_set) {
        cudaFuncSetAttribute(gemm_qkv,    cudaFuncAttributeMaxDynamicSharedMemorySize, GEMM_SMEM);
        cudaFuncSetAttribute(gemm_scores, cudaFuncAttributeMaxDynamicSharedMemorySize, GEMM_SMEM);
        cudaFuncSetAttribute(gemm_pv,     cudaFuncAttributeMaxDynamicSharedMemorySize, GEMM_SMEM);
        attr_set = 1;
    }

    // 0) inputs -> half
    cvt_h_kernel<<<1024, 256>>>(x, Xh, (long long)MTOT * BDIM);
    cvt3_h_kernel<<<dim3(512, 3), 256>>>(Wq, Wqh, Wk, Wkh, Wv, Wvh,
                                         (long long)BDIM * BDIM);

    // 1) fused QKV projection (V written transposed)
    dim3 gproj(BDIM / BNH, MTOT / BMH, 3);
    gemm_qkv<<<gproj, 256, GEMM_SMEM>>>(Xh, Wqh, Wkh, Wvh, Qh, Kh, Vth);

    // 2) scores + exp + causal mask + row partial sums (P unnormalized)
    dim3 gs(NSEQ / BNH, NSEQ / BMH, NB);
    gemm_scores<<<gs, 256, GEMM_SMEM>>>(Qh, Kh, P, Spart);

    // 3) fold partials -> inv
    sumrows_kernel<<<MTOT / 256, 256>>>(Spart, inv);

    // 4) O = inv * (P Vt^T) with causal k-limit
    dim3 go(BDIM / BNH, NSEQ / BMH, NB);
    gemm_pv<<<go, 256, GEMM_SMEM>>>(P, Vth, inv, out);
}

// round 17
// speedup vs baseline: 8.5750x; 1.1184x over previous
#include <cuda_runtime.h>
#include <cuda_fp16.h>
#include <math.h>
#include <stdint.h>

// Problem dims
#define NB    4
#define NSEQ  2048
#define BDIM  1024
#define MTOT  (NB * NSEQ)   // 8192

// GEMM tiling (fp16 mma.sync m16n8k16)
#define BMH 128
#define BNH 128
#define BKH 64
#define SKH 72                 // halves/row (64 + 8 pad) -> 144B stride
#define SKB (SKH * 2)          // row stride bytes
#define TILEH (BMH * SKH)      // halves per operand tile
#define STAGES 3
#define GEMM_SMEM (STAGES * 2 * TILEH * 2)   // 110592 B

// Scratch (device globals: allocation-free, per harness rules)
__device__ __half g_Xh  [(size_t)MTOT * BDIM];
__device__ __half g_Wqt [(size_t)BDIM * BDIM];   // Wq^T [in][out]
__device__ __half g_Wkt [(size_t)BDIM * BDIM];   // Wk^T [in][out]
__device__ __half g_Wvh [(size_t)BDIM * BDIM];   // Wv   [out][in]
__device__ __half g_Mt  [(size_t)BDIM * BDIM];   // (Wk^T Wq)/32, [j][i]
__device__ __half g_XM  [(size_t)MTOT * BDIM];   // X * Mt^T
__device__ __half g_Vth [(size_t)MTOT * BDIM];   // V transposed [b][d][t]
__device__ __half g_P   [(size_t)NB * NSEQ * NSEQ];  // unnormalized exp(S)
__device__ float  g_Spart[(size_t)16 * MTOT];    // per-kblock row partial sums
__device__ float  g_inv [(size_t)MTOT];          // 1/rowsum

// ---------------- PTX helpers ----------------
__device__ __forceinline__ uint32_t smem_u32(const void* p) {
    uint32_t a;
    asm("{ .reg .u64 t; cvta.to.shared.u64 t, %1; cvt.u32.u64 %0, t; }" : "=r"(a) : "l"(p));
    return a;
}
__device__ __forceinline__ void cp16s(uint32_t dst, const void* src) {
    asm volatile("cp.async.cg.shared.global [%0], [%1], 16;" :: "r"(dst), "l"(src));
}
__device__ __forceinline__ void cp_commit() { asm volatile("cp.async.commit_group;"); }
template <int N>
__device__ __forceinline__ void cp_wait() { asm volatile("cp.async.wait_group %0;" :: "n"(N)); }

__device__ __forceinline__ void ldm_x4(uint32_t* r, uint32_t addr) {
    asm volatile("ldmatrix.sync.aligned.m8n8.x4.shared.b16 {%0,%1,%2,%3}, [%4];"
                 : "=r"(r[0]), "=r"(r[1]), "=r"(r[2]), "=r"(r[3]) : "r"(addr));
}
__device__ __forceinline__ void mma_f16(float* c, const uint32_t* a, const uint32_t* b) {
    asm volatile(
        "mma.sync.aligned.m16n8k16.row.col.f32.f16.f16.f32 "
        "{%0,%1,%2,%3}, {%4,%5,%6,%7}, {%8,%9}, {%0,%1,%2,%3};"
        : "+f"(c[0]), "+f"(c[1]), "+f"(c[2]), "+f"(c[3])
        : "r"(a[0]), "r"(a[1]), "r"(a[2]), "r"(a[3]), "r"(b[0]), "r"(b[1]));
}

// ---------------------------------------------------------------------------
// Shared 3-stage cp.async mainloop: acc += A_tile * B_tile^T over T k-tiles.
// ---------------------------------------------------------------------------
__device__ __forceinline__ void gemm_mainloop(
    const __half* __restrict__ Ab, const __half* __restrict__ Bb,
    int K, int T, uint32_t sm0, int tid, uint32_t a_lane_off, uint32_t b_lane_off,
    float acc[4][4][4])
{
    const int ldr = tid >> 3, ldc = tid & 7;   // loader: row, 16B chunk

    auto load_tile = [&](int t) {
        const int buf = t % STAGES;
        const uint32_t as = sm0 + buf * 2 * TILEH * 2;
        const uint32_t bs = as + TILEH * 2;
        const int k0 = t * BKH;
        const uint32_t off = (uint32_t)ldr * SKB + ldc * 16;
        const __half* asrc = Ab + (size_t)ldr * K + k0 + ldc * 8;
        const __half* bsrc = Bb + (size_t)ldr * K + k0 + ldc * 8;
        #pragma unroll
        for (int i = 0; i < 4; i++) {
            cp16s(as + off + i * 32 * SKB, asrc + (size_t)32 * i * K);
            cp16s(bs + off + i * 32 * SKB, bsrc + (size_t)32 * i * K);
        }
        cp_commit();
    };

    load_tile(0);
    load_tile(1);

    for (int u = 0; u < T; u++) {
        if (u + 1 < T) cp_wait<1>(); else cp_wait<0>();
        __syncthreads();
        if (u + 2 < T) load_tile(u + 2);

        const int buf = u % STAGES;
        const uint32_t as = sm0 + buf * 2 * TILEH * 2;
        const uint32_t bs = as + TILEH * 2;

        #pragma unroll
        for (int ks = 0; ks < 4; ks++) {
            const int kk = ks * 16;
            uint32_t a[4][4], b[4][2];
            #pragma unroll
            for (int mf = 0; mf < 4; mf++)
                ldm_x4(a[mf], as + a_lane_off + (uint32_t)(mf * 16) * SKB + kk * 2);
            {
                uint32_t r0[4], r1[4];
                ldm_x4(r0, bs + b_lane_off + kk * 2);
                ldm_x4(r1, bs + b_lane_off + 16u * SKB + kk * 2);
                b[0][0] = r0[0]; b[0][1] = r0[1]; b[1][0] = r0[2]; b[1][1] = r0[3];
                b[2][0] = r1[0]; b[2][1] = r1[1]; b[3][0] = r1[2]; b[3][1] = r1[3];
            }
            #pragma unroll
            for (int mf = 0; mf < 4; mf++)
                #pragma unroll
                for (int nf = 0; nf < 4; nf++)
                    mma_f16(acc[mf][nf], a[mf], b[nf]);
        }
    }
}

#define GEMM_THREAD_IDS \
    const int tid  = threadIdx.x; \
    const int lane = tid & 31; \
    const int w    = tid >> 5; \
    const int wR = w >> 2, wC = w & 3; \
    const int gid = lane >> 2, tig = lane & 3; \
    const int mb = wR * 64, nb = wC * 32; \
    const uint32_t a_lane_off = (uint32_t)(mb + (lane & 15)) * SKB \
                              + (uint32_t)(lane >> 4) * 16; \
    const uint32_t b_lane_off = (uint32_t)(nb + (lane & 7) + ((lane >> 4) << 3)) * SKB \
                              + (uint32_t)((lane >> 3) & 1) * 16;

#define ACC_INIT \
    float acc[4][4][4]; \
    _Pragma("unroll") for (int i = 0; i < 4; i++) \
        _Pragma("unroll") for (int j = 0; j < 4; j++) \
            _Pragma("unroll") for (int r = 0; r < 4; r++) acc[i][j][r] = 0.f;

// ---------------------------------------------------------------------------
// Mt = (Wkt * Wqt^T) * (1/32):  Mt[j][i] = (1/32) * sum_o Wk[o,j]*Wq[o,i]
// Wkt/Wqt are [in][out] half K-major over o. Output half.
// ---------------------------------------------------------------------------
__global__ __launch_bounds__(256, 2)
void gemm_mt(const __half* __restrict__ Wkt, const __half* __restrict__ Wqt,
             __half* __restrict__ Mt)
{
    extern __shared__ __half sm[];
    GEMM_THREAD_IDS
    const uint32_t sm0 = smem_u32(sm);

    const __half* Ab = Wkt + (size_t)blockIdx.y * BMH * BDIM;
    const __half* Bb = Wqt + (size_t)blockIdx.x * BNH * BDIM;

    ACC_INIT
    gemm_mainloop(Ab, Bb, BDIM, BDIM / BKH, sm0, tid, a_lane_off, b_lane_off, acc);

    const float SC = 0.03125f;
    #pragma unroll
    for (int mf = 0; mf < 4; mf++) {
        int row = blockIdx.y * BMH + mb + mf * 16 + gid;
        #pragma unroll
        for (int nf = 0; nf < 4; nf++) {
            int col = blockIdx.x * BNH + nb + nf * 8 + tig * 2;
            *(__half2*)&Mt[(size_t)row * BDIM + col] =
                __floats2half2_rn(acc[mf][nf][0] * SC, acc[mf][nf][1] * SC);
            *(__half2*)&Mt[(size_t)(row + 8) * BDIM + col] =
                __floats2half2_rn(acc[mf][nf][2] * SC, acc[mf][nf][3] * SC);
        }
    }
}

// ---------------------------------------------------------------------------
// Fused projections: z=0 -> XM = X*Mt^T (half), z=1 -> V=X*Wv^T transposed
// into Vt[b][d][t]. One launch, grid (8, 64, 2).
// ---------------------------------------------------------------------------
__global__ __launch_bounds__(256, 2)
void gemm_xmv(const __half* __restrict__ X,
              const __half* __restrict__ Mt, const __half* __restrict__ Wv,
              __half* __restrict__ XM, __half* __restrict__ Vt)
{
    extern __shared__ __half sm[];
    GEMM_THREAD_IDS
    const uint32_t sm0 = smem_u32(sm);

    const int z = blockIdx.z;
    const __half* Bmat = (z == 0) ? Mt : Wv;

    const __half* Ab = X + (size_t)blockIdx.y * BMH * BDIM;
    const __half* Bb = Bmat + (size_t)blockIdx.x * BNH * BDIM;

    ACC_INIT
    gemm_mainloop(Ab, Bb, BDIM, BDIM / BKH, sm0, tid, a_lane_off, b_lane_off, acc);

    if (z == 0) {
        #pragma unroll
        for (int mf = 0; mf < 4; mf++) {
            int row = blockIdx.y * BMH + mb + mf * 16 + gid;
            #pragma unroll
            for (int nf = 0; nf < 4; nf++) {
                int col = blockIdx.x * BNH + nb + nf * 8 + tig * 2;
                *(__half2*)&XM[(size_t)row * BDIM + col] =
                    __floats2half2_rn(acc[mf][nf][0], acc[mf][nf][1]);
                *(__half2*)&XM[(size_t)(row + 8) * BDIM + col] =
                    __floats2half2_rn(acc[mf][nf][2], acc[mf][nf][3]);
            }
        }
    } else {
        __syncthreads();
        #define TSD 136
        __half* ts = sm;
        #pragma unroll
        for (int mf = 0; mf < 4; mf++) {
            int row = mb + mf * 16 + gid;
            #pragma unroll
            for (int nf = 0; nf < 4; nf++) {
                int col = nb + nf * 8 + tig * 2;
                ts[(col)     * TSD + row]     = __float2half_rn(acc[mf][nf][0]);
                ts[(col + 1) * TSD + row]     = __float2half_rn(acc[mf][nf][1]);
                ts[(col)     * TSD + row + 8] = __float2half_rn(acc[mf][nf][2]);
                ts[(col + 1) * TSD + row + 8] = __float2half_rn(acc[mf][nf][3]);
            }
        }
        __syncthreads();
        const int row0 = blockIdx.y * BMH;
        const int bz   = row0 >> 11;
        const int t0   = row0 & (NSEQ - 1);
        const int d    = tid >> 1;
        const int mh   = (tid & 1) * 64;
        __half* dst = Vt + (size_t)bz * BDIM * NSEQ
                    + (size_t)(blockIdx.x * BNH + d) * NSEQ + t0 + mh;
        const __half* src = ts + d * TSD + mh;
        #pragma unroll
        for (int i = 0; i < 8; i++)
            *(uint4*)(dst + i * 8) = *(const uint4*)(src + i * 8);
        #undef TSD
    }
}

// ---------------------------------------------------------------------------
// Scores S' = XM * X^T (scale pre-folded into Mt) + fused exp + causal mask
// + deterministic row partial sums. Unnormalized half P. Big rows first.
// ---------------------------------------------------------------------------
__global__ __launch_bounds__(256, 2)
void gemm_scores(const __half* __restrict__ XM, const __half* __restrict__ X,
                 __half* __restrict__ P, float* __restrict__ Spart)
{
    const int by = (int)gridDim.y - 1 - (int)blockIdx.y;   // big rows first
    const int bx = blockIdx.x;
    if (bx > by) return;

    extern __shared__ __half sm[];
    GEMM_THREAD_IDS
    const uint32_t sm0 = smem_u32(sm);
    const int z = blockIdx.z;

    const __half* Ab = XM + (size_t)z * NSEQ * BDIM + (size_t)by * BMH * BDIM;
    const __half* Bb = X  + (size_t)z * NSEQ * BDIM + (size_t)bx * BNH * BDIM;

    ACC_INIT
    gemm_mainloop(Ab, Bb, BDIM, BDIM / BKH, sm0, tid, a_lane_off, b_lane_off, acc);

    __syncthreads();
    float* rs = (float*)sm;                  // [128][4]
    const bool diag = (bx == by);
    __half* Pb = P + (size_t)z * NSEQ * NSEQ;

    #pragma unroll
    for (int mf = 0; mf < 4; mf++) {
        const int rl = mb + mf * 16 + gid;
        const int r0 = by * BMH + rl;
        float sA = 0.f, sB = 0.f;
        #pragma unroll
        for (int nf = 0; nf < 4; nf++) {
            int col = bx * BNH + nb + nf * 8 + tig * 2;
            float e0 = __expf(acc[mf][nf][0]);
            float e1 = __expf(acc[mf][nf][1]);
            float e2 = __expf(acc[mf][nf][2]);
            float e3 = __expf(acc[mf][nf][3]);
            if (diag) {
                if (col     > r0)     e0 = 0.f;
                if (col + 1 > r0)     e1 = 0.f;
                if (col     > r0 + 8) e2 = 0.f;
                if (col + 1 > r0 + 8) e3 = 0.f;
            }
            *(__half2*)&Pb[(size_t)r0 * NSEQ + col]       = __floats2half2_rn(e0, e1);
            *(__half2*)&Pb[(size_t)(r0 + 8) * NSEQ + col] = __floats2half2_rn(e2, e3);
            sA += e0 + e1;
            sB += e2 + e3;
        }
        sA += __shfl_xor_sync(0xffffffffu, sA, 1);
        sA += __shfl_xor_sync(0xffffffffu, sA, 2);
        sB += __shfl_xor_sync(0xffffffffu, sB, 1);
        sB += __shfl_xor_sync(0xffffffffu, sB, 2);
        if (tig == 0) {
            rs[rl * 4 + wC]       = sA;
            rs[(rl + 8) * 4 + wC] = sB;
        }
    }
    __syncthreads();
    if (tid < 128) {
        float t = rs[tid * 4] + rs[tid * 4 + 1] + rs[tid * 4 + 2] + rs[tid * 4 + 3];
        Spart[(size_t)bx * MTOT + (size_t)z * NSEQ + by * BMH + tid] = t;
    }
}

// ---------------------------------------------------------------------------
// Fold partial sums -> inv[row] (deterministic, fixed order)
// ---------------------------------------------------------------------------
__global__ void sumrows_kernel(const float* __restrict__ Spart,
                               float* __restrict__ inv)
{
    int r = blockIdx.x * 256 + threadIdx.x;     // 0..MTOT-1
    int q = r & (NSEQ - 1);
    int nblk = (q >> 7) + 1;
    float s = 0.f;
    for (int bx = 0; bx < nblk; bx++)
        s += Spart[(size_t)bx * MTOT + r];
    inv[r] = 1.f / s;
}

// ---------------------------------------------------------------------------
// PV: O[q,d] = inv[q] * sum_j P[q,j]*Vt[d,j], causal k-limit, big rows first.
// ---------------------------------------------------------------------------
__global__ __launch_bounds__(256, 2)
void gemm_pv(const __half* __restrict__ P, const __half* __restrict__ Vt,
             const float* __restrict__ inv, float* __restrict__ O)
{
    const int by = (int)gridDim.y - 1 - (int)blockIdx.y;   // big rows first
    extern __shared__ __half sm[];
    GEMM_THREAD_IDS
    const uint32_t sm0 = smem_u32(sm);
    const int z = blockIdx.z;

    const __half* Ab = P  + (size_t)z * NSEQ * NSEQ + (size_t)by * BMH * NSEQ;
    const __half* Bb = Vt + (size_t)z * BDIM * NSEQ + (size_t)blockIdx.x * BNH * NSEQ;
    const int T = (by + 1) * (BMH / BKH);

    ACC_INIT
    gemm_mainloop(Ab, Bb, NSEQ, T, sm0, tid, a_lane_off, b_lane_off, acc);

    float* Cb = O + (size_t)z * NSEQ * BDIM;
    #pragma unroll
    for (int mf = 0; mf < 4; mf++) {
        int row = by * BMH + mb + mf * 16 + gid;
        float iv0 = inv[(size_t)z * NSEQ + row];
        float iv1 = inv[(size_t)z * NSEQ + row + 8];
        #pragma unroll
        for (int nf = 0; nf < 4; nf++) {
            int col = blockIdx.x * BNH + nb + nf * 8 + tig * 2;
            *(float2*)&Cb[(size_t)row * BDIM + col] =
                make_float2(acc[mf][nf][0] * iv0, acc[mf][nf][1] * iv0);
            *(float2*)&Cb[(size_t)(row + 8) * BDIM + col] =
                make_float2(acc[mf][nf][2] * iv1, acc[mf][nf][3] * iv1);
        }
    }
}

// ---------------------------------------------------------------------------
// float -> half conversions
// ---------------------------------------------------------------------------
__global__ void cvt_h_kernel(const float* __restrict__ in, __half* __restrict__ out,
                             long long n)
{
    long long i = (long long)blockIdx.x * blockDim.x + threadIdx.x;
    long long stride = (long long)gridDim.x * blockDim.x;
    for (; i < n; i += stride)
        out[i] = __float2half_rn(in[i]);
}

// Transposing convert: in fp32 [out][in] row-major -> half [in][out]
// z = 0: Wq -> Wqt, z = 1: Wk -> Wkt
__global__ __launch_bounds__(256)
void cvt_wt_kernel(const float* __restrict__ Wq, const float* __restrict__ Wk,
                   __half* __restrict__ Wqt, __half* __restrict__ Wkt)
{
    __shared__ float tb[32][33];
    const float* in = (blockIdx.z == 0) ? Wq : Wk;
    __half*     out = (blockIdx.z == 0) ? Wqt : Wkt;
    const int o0 = blockIdx.x * 32;   // row of in
    const int i0 = blockIdx.y * 32;   // col of in
    const int x = threadIdx.x & 31, y = threadIdx.x >> 5;   // 32 x 8
    #pragma unroll
    for (int r = 0; r < 32; r += 8)
        tb[y + r][x] = in[(size_t)(o0 + y + r) * BDIM + i0 + x];
    __syncthreads();
    #pragma unroll
    for (int r = 0; r < 32; r += 8)
        out[(size_t)(i0 + y + r) * BDIM + o0 + x] = __float2half_rn(tb[x][y + r]);
}

// ---------------------------------------------------------------------------
extern "C" void kernel_launch(void* const* d_in, const int* in_sizes, int n_in,
                              void* d_out, int out_size)
{
    const float* x  = (const float*)d_in[0];
    const float* Wq = (const float*)d_in[1];
    const float* Wk = (const float*)d_in[2];
    const float* Wv = (const float*)d_in[3];
    float* out = (float*)d_out;

    __half *Xh, *Wqt, *Wkt, *Wvh, *Mt, *XM, *Vth, *P;
    float *Spart, *inv;
    cudaGetSymbolAddress((void**)&Xh,   g_Xh);
    cudaGetSymbolAddress((void**)&Wqt,  g_Wqt);
    cudaGetSymbolAddress((void**)&Wkt,  g_Wkt);
    cudaGetSymbolAddress((void**)&Wvh,  g_Wvh);
    cudaGetSymbolAddress((void**)&Mt,   g_Mt);
    cudaGetSymbolAddress((void**)&XM,   g_XM);
    cudaGetSymbolAddress((void**)&Vth,  g_Vth);
    cudaGetSymbolAddress((void**)&P,    g_P);
    cudaGetSymbolAddress((void**)&Spart, g_Spart);
    cudaGetSymbolAddress((void**)&inv,  g_inv);

    static int attr_set = 0;
    if (!attr_set) {
        cudaFuncSetAttribute(gemm_mt,     cudaFuncAttributeMaxDynamicSharedMemorySize, GEMM_SMEM);
        cudaFuncSetAttribute(gemm_xmv,    cudaFuncAttributeMaxDynamicSharedMemorySize, GEMM_SMEM);
        cudaFuncSetAttribute(gemm_scores, cudaFuncAttributeMaxDynamicSharedMemorySize, GEMM_SMEM);
        cudaFuncSetAttribute(gemm_pv,     cudaFuncAttributeMaxDynamicSharedMemorySize, GEMM_SMEM);
        attr_set = 1;
    }

    // 0) conversions: x -> Xh; Wq/Wk -> transposed half; Wv -> half
    cvt_h_kernel<<<1024, 256>>>(x, Xh, (long long)MTOT * BDIM);
    cvt_wt_kernel<<<dim3(32, 32, 2), 256>>>(Wq, Wk, Wqt, Wkt);
    cvt_h_kernel<<<512, 256>>>(Wv, Wvh, (long long)BDIM * BDIM);

    // 1) Mt = (Wk^T * Wq) / 32   [j][i], half
    gemm_mt<<<dim3(8, 8, 1), 256, GEMM_SMEM>>>(Wkt, Wqt, Mt);

    // 2) fused projections: XM = X*Mt^T; V = X*Wv^T written transposed
    gemm_xmv<<<dim3(8, 64, 2), 256, GEMM_SMEM>>>(Xh, Mt, Wvh, XM, Vth);

    // 3) scores S' = XM * X^T (+exp, causal mask, partial row sums)
    dim3 gs(NSEQ / BNH, NSEQ / BMH, NB);
    gemm_scores<<<gs, 256, GEMM_SMEM>>>(XM, Xh, P, Spart);

    // 4) fold partials -> inv
    sumrows_kernel<<<MTOT / 256, 256>>>(Spart, inv);

    // 5) O = inv * (P Vt^T) with causal k-limit
    dim3 go(BDIM / BNH, NSEQ / BMH, NB);
    gemm_pv<<<go, 256, GEMM_SMEM>>>(P, Vth, inv, out);
}